// round 12
// baseline (speedup 1.0000x reference)
#include <cuda_runtime.h>
#include <cuda_fp16.h>
#include <cstdint>
#include <math.h>

#define S_LEN    2048
#define D_MODEL  1024
#define N_HEADS  16
#define D_HEAD   64
#define D_MLP    4096
#define N_LAYERS 4
#define N_VOCAB  50257
#define N_VOCAB_PAD 50432   // 197*256
#define N_TOKENS 4096       // B*S
#define QKV_N    3072

// -------------------- scratch --------------------
__device__ float  g_resid[N_TOKENS * D_MODEL];
__device__ __half g_xh   [N_TOKENS * D_MODEL];
__device__ __half g_qkvh [N_TOKENS * QKV_N];
__device__ __half g_zh   [N_TOKENS * D_MODEL];
__device__ __half g_hh   [N_TOKENS * D_MLP];
__device__ __half g_wqkv [N_LAYERS * D_MODEL * QKV_N];
__device__ float  g_bqkv [N_LAYERS * QKV_N];
__device__ __half g_wo   [N_LAYERS * D_MODEL * D_MODEL];
__device__ __half g_win  [N_LAYERS * D_MODEL * D_MLP];
__device__ __half g_wout [N_LAYERS * D_MLP * D_MODEL];
__device__ __half g_wu   [D_MODEL * N_VOCAB_PAD];

#define WO_ELEMS  (N_LAYERS * D_MODEL * D_MODEL)
#define WIN_ELEMS (N_LAYERS * D_MODEL * D_MLP)
#define WOUT_ELEMS (N_LAYERS * D_MLP * D_MODEL)
#define FLAT3_ELEMS (WO_ELEMS + WIN_ELEMS + WOUT_ELEMS)

// -------------------- helpers --------------------
__device__ __forceinline__ float gelu_new(float x) {
  float u = 0.7978845608028654f * (x + 0.044715f * x * x * x);
  return 0.5f * x * (1.0f + tanhf(u));
}
__device__ __forceinline__ void ldsm_x4(uint32_t (&r)[4], uint32_t addr) {
  asm volatile("ldmatrix.sync.aligned.m8n8.x4.shared.b16 {%0,%1,%2,%3}, [%4];"
    : "=r"(r[0]), "=r"(r[1]), "=r"(r[2]), "=r"(r[3]) : "r"(addr));
}
__device__ __forceinline__ void ldsm_x4_t(uint32_t (&r)[4], uint32_t addr) {
  asm volatile("ldmatrix.sync.aligned.m8n8.x4.trans.shared.b16 {%0,%1,%2,%3}, [%4];"
    : "=r"(r[0]), "=r"(r[1]), "=r"(r[2]), "=r"(r[3]) : "r"(addr));
}
__device__ __forceinline__ void mma_f16(float (&c)[4], const uint32_t (&a)[4],
                                        const uint32_t b0, const uint32_t b1) {
  asm volatile("mma.sync.aligned.m16n8k16.row.col.f32.f16.f16.f32 "
    "{%0,%1,%2,%3}, {%4,%5,%6,%7}, {%8,%9}, {%0,%1,%2,%3};"
    : "+f"(c[0]), "+f"(c[1]), "+f"(c[2]), "+f"(c[3])
    : "r"(a[0]), "r"(a[1]), "r"(a[2]), "r"(a[3]), "r"(b0), "r"(b1));
}
__device__ __forceinline__ void cp_async16(uint32_t dst, const void* src) {
  asm volatile("cp.async.cg.shared.global [%0], [%1], 16;\n" :: "r"(dst), "l"(src));
}
__device__ __forceinline__ uint4 pack8(const float4 a, const float4 b) {
  __half2 h0 = __floats2half2_rn(a.x, a.y);
  __half2 h1 = __floats2half2_rn(a.z, a.w);
  __half2 h2 = __floats2half2_rn(b.x, b.y);
  __half2 h3 = __floats2half2_rn(b.z, b.w);
  uint4 r;
  r.x = *reinterpret_cast<uint32_t*>(&h0);
  r.y = *reinterpret_cast<uint32_t*>(&h1);
  r.z = *reinterpret_cast<uint32_t*>(&h2);
  r.w = *reinterpret_cast<uint32_t*>(&h3);
  return r;
}

// -------------------- weight conversion --------------------
__global__ __launch_bounds__(256) void conv_flat3(
    const float* __restrict__ wo_in, const float* __restrict__ win_in,
    const float* __restrict__ wout_in,
    __half* __restrict__ wo_out, __half* __restrict__ win_out,
    __half* __restrict__ wout_out) {
  size_t i8 = ((size_t)blockIdx.x * 256 + threadIdx.x) * 8;
  const float* src;
  __half* dst;
  size_t off;
  if (i8 < WO_ELEMS) {
    src = wo_in; dst = wo_out; off = i8;
  } else if (i8 < WO_ELEMS + WIN_ELEMS) {
    src = win_in; dst = win_out; off = i8 - WO_ELEMS;
  } else {
    src = wout_in; dst = wout_out; off = i8 - WO_ELEMS - WIN_ELEMS;
  }
  float4 a = *reinterpret_cast<const float4*>(src + off);
  float4 b = *reinterpret_cast<const float4*>(src + off + 4);
  *reinterpret_cast<uint4*>(dst + off) = pack8(a, b);
}
__global__ __launch_bounds__(256) void conv_qkv8(
    const float* __restrict__ WQ, const float* __restrict__ WK,
    const float* __restrict__ WV, __half* __restrict__ out) {
  size_t i8 = ((size_t)blockIdx.x * 256 + threadIdx.x) * 8;
  int n = (int)(i8 % QKV_N);
  size_t lk = i8 / QKV_N;
  int k = (int)(lk % D_MODEL);
  int l = (int)(lk / D_MODEL);
  int which = n >> 10, nn = n & 1023;
  int h = nn >> 6, dh = nn & 63;
  const float* W = (which == 0) ? WQ : ((which == 1) ? WK : WV);
  const float* src = W + (((size_t)l * N_HEADS + h) * D_MODEL + k) * D_HEAD + dh;
  float4 a = *reinterpret_cast<const float4*>(src);
  float4 b = *reinterpret_cast<const float4*>(src + 4);
  *reinterpret_cast<uint4*>(out + i8) = pack8(a, b);
}
__global__ __launch_bounds__(256) void conv_vocab8(
    const float* __restrict__ in, __half* __restrict__ out) {
  int k = blockIdx.y;
  int n = blockIdx.x * 2048 + threadIdx.x * 8;
  if (n >= N_VOCAB_PAD) return;
  const float* row = in + (size_t)k * N_VOCAB;
  float f[8];
#pragma unroll
  for (int u = 0; u < 8; u++) {
    int c = n + u;
    f[u] = (c < N_VOCAB) ? __ldg(row + c) : 0.f;
  }
  float4 a = make_float4(f[0], f[1], f[2], f[3]);
  float4 b = make_float4(f[4], f[5], f[6], f[7]);
  *reinterpret_cast<uint4*>(out + (size_t)k * N_VOCAB_PAD + n) = pack8(a, b);
}
__global__ __launch_bounds__(256) void pack_bias_qkv(
    const float* __restrict__ bq, const float* __restrict__ bk,
    const float* __restrict__ bv, float* __restrict__ out) {
  int i = blockIdx.x * 256 + threadIdx.x;
  int n = i % QKV_N, l = i / QKV_N;
  const float* s = (n < 1024) ? bq : ((n < 2048) ? bk : bv);
  out[i] = s[l * 1024 + (n & 1023)];
}

// -------------------- embedding --------------------
__global__ __launch_bounds__(256) void embed_kernel(
    const int* __restrict__ tok, const float* __restrict__ WE,
    const float* __restrict__ Wp, float* __restrict__ out) {
  int row = blockIdx.x;
  int s = row & (S_LEN - 1);
  int t = threadIdx.x;
  int token = tok[row];
  float4 e = reinterpret_cast<const float4*>(WE + (size_t)token * D_MODEL)[t];
  float4 p = reinterpret_cast<const float4*>(Wp + (size_t)s * D_MODEL)[t];
  float4 r;
  r.x = e.x + p.x; r.y = e.y + p.y; r.z = e.z + p.z; r.w = e.w + p.w;
  reinterpret_cast<float4*>(out + (size_t)row * D_MODEL)[t] = r;
}

// -------------------- layernorm --------------------
__global__ __launch_bounds__(256) void ln_kernel(
    const float* __restrict__ in, const float* __restrict__ w,
    const float* __restrict__ b, __half* __restrict__ out) {
  int row = blockIdx.x;
  int t = threadIdx.x;
  float4 v = reinterpret_cast<const float4*>(in + (size_t)row * D_MODEL)[t];
  float s  = v.x + v.y + v.z + v.w;
  float ss = v.x*v.x + v.y*v.y + v.z*v.z + v.w*v.w;
#pragma unroll
  for (int off = 16; off; off >>= 1) {
    s  += __shfl_xor_sync(0xffffffffu, s,  off);
    ss += __shfl_xor_sync(0xffffffffu, ss, off);
  }
  __shared__ float shs[8], shss[8];
  int wid = t >> 5;
  if ((t & 31) == 0) { shs[wid] = s; shss[wid] = ss; }
  __syncthreads();
  float tot = 0.f, tots = 0.f;
#pragma unroll
  for (int i = 0; i < 8; i++) { tot += shs[i]; tots += shss[i]; }
  float mean = tot * (1.0f / D_MODEL);
  float var  = tots * (1.0f / D_MODEL) - mean * mean;
  float rstd = rsqrtf(var + 1e-5f);
  float4 wv = reinterpret_cast<const float4*>(w)[t];
  float4 bv = reinterpret_cast<const float4*>(b)[t];
  float ox = (v.x - mean) * rstd * wv.x + bv.x;
  float oy = (v.y - mean) * rstd * wv.y + bv.y;
  float oz = (v.z - mean) * rstd * wv.z + bv.z;
  float ow = (v.w - mean) * rstd * wv.w + bv.w;
  __half2* o2 = reinterpret_cast<__half2*>(out + (size_t)row * D_MODEL);
  o2[2 * t]     = __floats2half2_rn(ox, oy);
  o2[2 * t + 1] = __floats2half2_rn(oz, ow);
}

// -------------------- FP16 tensor-core GEMM (128x256, 512 thr, warp 32x64) -
// Halves L2 traffic per FLOP vs 128x128 (48KB per 4.2MF instead of 35.8KB
// per 2.1MF) — the GEMM was LTS-bandwidth-bound at ~9.8 TB/s demand.
#define KT        64
#define LDA_B     144     // A row: 64 halves + pad (bank ≡4 mod 32, conflict-free)
#define LDB_B     528     // B row: 256 halves + pad (132 banks ≡4 mod 32)
#define A_BYTES   (128 * LDA_B)   // 18432
#define B_BYTES   (KT * LDB_B)    // 33792
#define STAGE_B   (A_BYTES + B_BYTES)  // 52224
#define NSTAGES   3
#define GEMM_SMEM (NSTAGES * STAGE_B)  // 156672

template<bool GELU, bool ACCUM, bool OUTH, bool SWAP>
__global__ __launch_bounds__(512) void hgemm(
    const __half* __restrict__ A, const __half* __restrict__ B,
    const float* __restrict__ bias, void* __restrict__ Cv,
    int M, int K, int NB, int Nstore) {
  extern __shared__ __align__(16) char smem[];
  const uint32_t sm = (uint32_t)__cvta_generic_to_shared(smem);

  const int tid  = threadIdx.x;
  const int lane = tid & 31, warp = tid >> 5;      // 16 warps
  const int wm = (warp >> 2) * 32;                 // 4 warp-rows of 32
  const int wn = (warp & 3) * 64;                  // 4 warp-cols of 64
  const int g = lane >> 2, t = lane & 3;
  const int brow = (SWAP ? blockIdx.x : blockIdx.y) * 128;
  const int bcol = (SWAP ? blockIdx.y : blockIdx.x) * 256;
  const uint32_t laneRow = lane & 15, laneHi = lane >> 4;

  float acc[16][4];
#pragma unroll
  for (int i = 0; i < 16; i++)
#pragma unroll
    for (int j = 0; j < 4; j++) acc[i][j] = 0.f;

  const int NT = K / KT;

  auto stage = [&](int tt) {
    const int k0 = tt * KT;
    const uint32_t sA = sm + (uint32_t)(tt % NSTAGES) * STAGE_B;
    const uint32_t sB = sA + A_BYTES;
    // A: 128 rows x 64 halves = 1024 16B-chunks (512 thr x 2)
    {
      int slot = tid;
#pragma unroll
      for (int i = 0; i < 2; i++) {
        int r = slot >> 3, ch = slot & 7;
        cp_async16(sA + (uint32_t)r * LDA_B + ch * 16,
                   A + (size_t)(brow + r) * K + k0 + ch * 8);
        slot += 512;
      }
    }
    // B: 64 rows x 256 halves = 2048 16B-chunks (512 thr x 4)
    {
      int slot = tid;
#pragma unroll
      for (int i = 0; i < 4; i++) {
        int r = slot >> 5, ch = slot & 31;
        cp_async16(sB + (uint32_t)r * LDB_B + ch * 16,
                   B + (size_t)(k0 + r) * NB + bcol + ch * 8);
        slot += 512;
      }
    }
    asm volatile("cp.async.commit_group;\n" ::: "memory");
  };

  stage(0);
  if (NT > 1) stage(1);

  for (int tt = 0; tt < NT; tt++) {
    if (tt + 1 < NT) {
      asm volatile("cp.async.wait_group 1;\n" ::: "memory");
    } else {
      asm volatile("cp.async.wait_group 0;\n" ::: "memory");
    }
    __syncthreads();
    if (tt + 2 < NT) stage(tt + 2);

    const uint32_t sA = sm + (uint32_t)(tt % NSTAGES) * STAGE_B;
    const uint32_t sB = sA + A_BYTES;

#pragma unroll
    for (int ik = 0; ik < 4; ik++) {
      uint32_t a[2][4];
#pragma unroll
      for (int im = 0; im < 2; im++)
        ldsm_x4(a[im], sA + (uint32_t)(wm + im * 16 + laneRow) * LDA_B
                          + ik * 32 + laneHi * 16);
      uint32_t b[8][2];
#pragma unroll
      for (int jp = 0; jp < 4; jp++) {
        uint32_t r[4];
        ldsm_x4_t(r, sB + (uint32_t)(ik * 16 + laneRow) * LDB_B
                        + (uint32_t)(wn + jp * 16 + laneHi * 8) * 2);
        b[2 * jp][0] = r[0]; b[2 * jp][1] = r[1];
        b[2 * jp + 1][0] = r[2]; b[2 * jp + 1][1] = r[3];
      }
#pragma unroll
      for (int im = 0; im < 2; im++)
#pragma unroll
        for (int jn = 0; jn < 8; jn++)
          mma_f16(acc[im * 8 + jn], a[im], b[jn][0], b[jn][1]);
    }
    __syncthreads();
  }

  float*  Cf = (float*)Cv;
  __half* Ch = (__half*)Cv;
#pragma unroll
  for (int im = 0; im < 2; im++) {
#pragma unroll
    for (int jn = 0; jn < 8; jn++) {
      const float* c = acc[im * 8 + jn];
      int r0 = brow + wm + im * 16 + g;
      int c0 = bcol + wn + jn * 8 + 2 * t;
#pragma unroll
      for (int u = 0; u < 4; u++) {
        int r = r0 + (u >> 1) * 8;
        int cc = c0 + (u & 1);
        if (cc < Nstore) {
          float val = c[u] + bias[cc];
          if (GELU) val = gelu_new(val);
          size_t idx = (size_t)r * Nstore + cc;
          if (OUTH) {
            Ch[idx] = __float2half(val);
          } else {
            if (ACCUM) val += Cf[idx];
            Cf[idx] = val;
          }
        }
      }
    }
  }
}

// -------------------- tensor-core flash attention --------------------
#define ATT_LD 144
__global__ __launch_bounds__(128) void attn_tc(
    const __half* __restrict__ qkv, __half* __restrict__ z) {
  const int b = blockIdx.z, h = blockIdx.y;
  const int q0 = (gridDim.x - 1 - blockIdx.x) * 64;
  const int tid = threadIdx.x;
  const int warp = tid >> 5, lane = tid & 31;
  const int g = lane >> 2, t = lane & 3;

  __shared__ __align__(16) __half sQ[64 * 72];
  __shared__ __align__(16) __half sK[2][64 * 72];
  __shared__ __align__(16) __half sV[2][64 * 72];
  const uint32_t qb = (uint32_t)__cvta_generic_to_shared(sQ);
  const uint32_t kb0 = (uint32_t)__cvta_generic_to_shared(sK[0]);
  const uint32_t kb1 = (uint32_t)__cvta_generic_to_shared(sK[1]);
  const uint32_t vb0 = (uint32_t)__cvta_generic_to_shared(sV[0]);
  const uint32_t vb1 = (uint32_t)__cvta_generic_to_shared(sV[1]);

  for (int slot = tid; slot < 512; slot += 128) {
    int r = slot >> 3, c = slot & 7;
    *reinterpret_cast<uint4*>(&sQ[r * 72 + c * 8]) =
      *reinterpret_cast<const uint4*>(
        qkv + (size_t)(b * S_LEN + q0 + r) * QKV_N + h * D_HEAD + c * 8);
  }
  __syncthreads();

  uint32_t qf[4][4];
#pragma unroll
  for (int ik = 0; ik < 4; ik++)
    ldsm_x4(qf[ik], qb + (uint32_t)(warp * 16 + (lane & 15)) * ATT_LD
                       + ik * 32 + (lane >> 4) * 16);

  const int row0 = q0 + warp * 16 + g;
  const int row1 = row0 + 8;

  float m0 = -INFINITY, m1 = -INFINITY, l0 = 0.f, l1 = 0.f;
  float oacc[8][4];
#pragma unroll
  for (int i = 0; i < 8; i++)
#pragma unroll
    for (int j = 0; j < 4; j++) oacc[i][j] = 0.f;

  const int ntiles = (q0 >> 6) + 1;

  auto stageKV = [&](int tile) {
    const int kt = tile * 64;
    const uint32_t kd = (tile & 1) ? kb1 : kb0;
    const uint32_t vd = (tile & 1) ? vb1 : vb0;
    for (int slot = tid; slot < 512; slot += 128) {
      int r = slot >> 3, c = slot & 7;
      const __half* src = qkv + (size_t)(b * S_LEN + kt + r) * QKV_N
                              + 1024 + h * D_HEAD + c * 8;
      cp_async16(kd + (uint32_t)r * ATT_LD + c * 16, src);
      cp_async16(vd + (uint32_t)r * ATT_LD + c * 16, src + 1024);
    }
    asm volatile("cp.async.commit_group;\n" ::: "memory");
  };

  stageKV(0);

  for (int tile = 0; tile < ntiles; tile++) {
    asm volatile("cp.async.wait_group 0;\n" ::: "memory");
    __syncthreads();
    if (tile + 1 < ntiles) stageKV(tile + 1);

    const uint32_t kd = (tile & 1) ? kb1 : kb0;
    const uint32_t vd = (tile & 1) ? vb1 : vb0;
    const int kt = tile * 64;

    float sacc[8][4];
#pragma unroll
    for (int j = 0; j < 8; j++) {
#pragma unroll
      for (int u = 0; u < 4; u++) sacc[j][u] = 0.f;
      uint32_t bk0[4], bk1[4];
      uint32_t base = kd + (uint32_t)(j * 8 + (lane & 7)) * ATT_LD + (lane >> 3) * 16;
      ldsm_x4(bk0, base);
      ldsm_x4(bk1, base + 64);
      mma_f16(sacc[j], qf[0], bk0[0], bk0[1]);
      mma_f16(sacc[j], qf[1], bk0[2], bk0[3]);
      mma_f16(sacc[j], qf[2], bk1[0], bk1[1]);
      mma_f16(sacc[j], qf[3], bk1[2], bk1[3]);
    }

    float tmx0 = -1e30f, tmx1 = -1e30f;
#pragma unroll
    for (int j = 0; j < 8; j++) {
      int kbase = kt + j * 8 + 2 * t;
      sacc[j][0] = (kbase     <= row0) ? sacc[j][0] * 0.125f : -1e30f;
      sacc[j][1] = (kbase + 1 <= row0) ? sacc[j][1] * 0.125f : -1e30f;
      sacc[j][2] = (kbase     <= row1) ? sacc[j][2] * 0.125f : -1e30f;
      sacc[j][3] = (kbase + 1 <= row1) ? sacc[j][3] * 0.125f : -1e30f;
      tmx0 = fmaxf(tmx0, fmaxf(sacc[j][0], sacc[j][1]));
      tmx1 = fmaxf(tmx1, fmaxf(sacc[j][2], sacc[j][3]));
    }
#pragma unroll
    for (int off = 1; off <= 2; off <<= 1) {
      tmx0 = fmaxf(tmx0, __shfl_xor_sync(0xffffffffu, tmx0, off));
      tmx1 = fmaxf(tmx1, __shfl_xor_sync(0xffffffffu, tmx1, off));
    }
    float mn0 = fmaxf(m0, tmx0), mn1 = fmaxf(m1, tmx1);
    float corr0 = __expf(m0 - mn0), corr1 = __expf(m1 - mn1);
    m0 = mn0; m1 = mn1;

    uint32_t pf[8][2];
    float sum0 = 0.f, sum1 = 0.f;
#pragma unroll
    for (int j = 0; j < 8; j++) {
      float p0 = __expf(sacc[j][0] - mn0);
      float p1 = __expf(sacc[j][1] - mn0);
      float p2 = __expf(sacc[j][2] - mn1);
      float p3 = __expf(sacc[j][3] - mn1);
      sum0 += p0 + p1; sum1 += p2 + p3;
      __half2 h01 = __floats2half2_rn(p0, p1);
      __half2 h23 = __floats2half2_rn(p2, p3);
      pf[j][0] = *reinterpret_cast<uint32_t*>(&h01);
      pf[j][1] = *reinterpret_cast<uint32_t*>(&h23);
    }
#pragma unroll
    for (int off = 1; off <= 2; off <<= 1) {
      sum0 += __shfl_xor_sync(0xffffffffu, sum0, off);
      sum1 += __shfl_xor_sync(0xffffffffu, sum1, off);
    }
    l0 = l0 * corr0 + sum0;
    l1 = l1 * corr1 + sum1;
#pragma unroll
    for (int np = 0; np < 8; np++) {
      oacc[np][0] *= corr0; oacc[np][1] *= corr0;
      oacc[np][2] *= corr1; oacc[np][3] *= corr1;
    }

#pragma unroll
    for (int kk = 0; kk < 4; kk++) {
      uint32_t a[4] = { pf[2 * kk][0], pf[2 * kk][1],
                        pf[2 * kk + 1][0], pf[2 * kk + 1][1] };
#pragma unroll
      for (int np = 0; np < 4; np++) {
        uint32_t r[4];
        ldsm_x4_t(r, vd + (uint32_t)(kk * 16 + (lane & 15)) * ATT_LD
                        + np * 32 + (lane >> 4) * 16);
        mma_f16(oacc[2 * np], a, r[0], r[1]);
        mma_f16(oacc[2 * np + 1], a, r[2], r[3]);
      }
    }
    __syncthreads();
  }

  const float inv0 = 1.0f / l0, inv1 = 1.0f / l1;
#pragma unroll
  for (int np = 0; np < 8; np++) {
    int col = h * D_HEAD + np * 8 + 2 * t;
    __half2 lo = __floats2half2_rn(oacc[np][0] * inv0, oacc[np][1] * inv0);
    __half2 hi = __floats2half2_rn(oacc[np][2] * inv1, oacc[np][3] * inv1);
    *reinterpret_cast<__half2*>(&z[(size_t)(b * S_LEN + row0) * D_MODEL + col]) = lo;
    *reinterpret_cast<__half2*>(&z[(size_t)(b * S_LEN + row1) * D_MODEL + col]) = hi;
  }
}

// -------------------- driver --------------------
template<bool GELU, bool ACCUM, bool OUTH, bool SWAP>
static void launch_hgemm(const __half* A, const __half* B, const float* bias,
                         void* C, int M, int K, int NB, int Nstore) {
  cudaFuncSetAttribute(hgemm<GELU, ACCUM, OUTH, SWAP>,
                       cudaFuncAttributeMaxDynamicSharedMemorySize, GEMM_SMEM);
  dim3 grid = SWAP ? dim3(M / 128, NB / 256) : dim3(NB / 256, M / 128);
  hgemm<GELU, ACCUM, OUTH, SWAP><<<grid, 512, GEMM_SMEM>>>(A, B, bias, C, M, K, NB, Nstore);
}

extern "C" void kernel_launch(void* const* d_in, const int* in_sizes, int n_in,
                              void* d_out, int out_size) {
  const int*   tokens = (const int*)  d_in[0];
  const float* W_E    = (const float*)d_in[1];
  const float* W_pos  = (const float*)d_in[2];
  const float* ln1_w  = (const float*)d_in[3];
  const float* ln1_b  = (const float*)d_in[4];
  const float* W_Q    = (const float*)d_in[5];
  const float* b_Q    = (const float*)d_in[6];
  const float* W_K    = (const float*)d_in[7];
  const float* b_K    = (const float*)d_in[8];
  const float* W_V    = (const float*)d_in[9];
  const float* b_V    = (const float*)d_in[10];
  const float* W_O    = (const float*)d_in[11];
  const float* b_O    = (const float*)d_in[12];
  const float* ln2_w  = (const float*)d_in[13];
  const float* ln2_b  = (const float*)d_in[14];
  const float* W_in   = (const float*)d_in[15];
  const float* b_in   = (const float*)d_in[16];
  const float* W_out  = (const float*)d_in[17];
  const float* b_out  = (const float*)d_in[18];
  const float* lnf_w  = (const float*)d_in[19];
  const float* lnf_b  = (const float*)d_in[20];
  const float* W_U    = (const float*)d_in[21];
  const float* b_U    = (const float*)d_in[22];
  float* out = (float*)d_out;

  float *resid, *bqkv;
  __half *xh, *qkvh, *zh, *hh, *wqkv, *wo, *win, *wout, *wu;
  cudaGetSymbolAddress((void**)&resid, g_resid);
  cudaGetSymbolAddress((void**)&xh,    g_xh);
  cudaGetSymbolAddress((void**)&qkvh,  g_qkvh);
  cudaGetSymbolAddress((void**)&zh,    g_zh);
  cudaGetSymbolAddress((void**)&hh,    g_hh);
  cudaGetSymbolAddress((void**)&wqkv,  g_wqkv);
  cudaGetSymbolAddress((void**)&bqkv,  g_bqkv);
  cudaGetSymbolAddress((void**)&wo,    g_wo);
  cudaGetSymbolAddress((void**)&win,   g_win);
  cudaGetSymbolAddress((void**)&wout,  g_wout);
  cudaGetSymbolAddress((void**)&wu,    g_wu);

  conv_qkv8<<<(N_LAYERS * D_MODEL * QKV_N) / 2048, 256>>>(W_Q, W_K, W_V, wqkv);
  pack_bias_qkv<<<(N_LAYERS * QKV_N) / 256, 256>>>(b_Q, b_K, b_V, bqkv);
  conv_flat3<<<FLAT3_ELEMS / 2048, 256>>>(W_O, W_in, W_out, wo, win, wout);
  embed_kernel<<<N_TOKENS, 256>>>(tokens, W_E, W_pos, resid);

  dim3 gA(S_LEN / 64, N_HEADS, 2);

  for (int l = 0; l < N_LAYERS; l++) {
    size_t w1 = (size_t)l * D_MODEL * D_MODEL;
    size_t w2 = (size_t)l * D_MODEL * D_MLP;
    const float* l1w = ln1_w + (size_t)l * D_MODEL;
    const float* l1b = ln1_b + (size_t)l * D_MODEL;
    const float* l2w = ln2_w + (size_t)l * D_MODEL;
    const float* l2b = ln2_b + (size_t)l * D_MODEL;

    ln_kernel<<<N_TOKENS, 256>>>(resid, l1w, l1b, xh);
    launch_hgemm<false, false, true, false>(xh, wqkv + (size_t)l * D_MODEL * QKV_N,
                                            bqkv + (size_t)l * QKV_N, qkvh,
                                            N_TOKENS, D_MODEL, QKV_N, QKV_N);
    attn_tc<<<gA, 128>>>(qkvh, zh);
    launch_hgemm<false, true, false, false>(zh, wo + w1, b_O + (size_t)l * D_MODEL, resid,
                                            N_TOKENS, D_MODEL, D_MODEL, D_MODEL);
    ln_kernel<<<N_TOKENS, 256>>>(resid, l2w, l2b, xh);
    launch_hgemm<true, false, true, false>(xh, win + w2, b_in + (size_t)l * D_MLP, hh,
                                           N_TOKENS, D_MODEL, D_MLP, D_MLP);
    launch_hgemm<false, true, false, false>(hh, wout + w2, b_out + (size_t)l * D_MODEL, resid,
                                            N_TOKENS, D_MLP, D_MODEL, D_MODEL);
  }

  ln_kernel<<<N_TOKENS, 256>>>(resid, lnf_w, lnf_b, xh);
  {
    dim3 gv((N_VOCAB_PAD + 2047) / 2048, D_MODEL);
    conv_vocab8<<<gv, 256>>>(W_U, wu);
  }
  launch_hgemm<false, false, false, true>(xh, wu, b_U, out,
                                          N_TOKENS, D_MODEL, N_VOCAB_PAD, N_VOCAB);
}

// round 13
// speedup vs baseline: 1.0399x; 1.0399x over previous
#include <cuda_runtime.h>
#include <cuda_fp16.h>
#include <cstdint>
#include <math.h>

#define S_LEN    2048
#define D_MODEL  1024
#define N_HEADS  16
#define D_HEAD   64
#define D_MLP    4096
#define N_LAYERS 4
#define N_VOCAB  50257
#define N_VOCAB_PAD 50432
#define N_TOKENS 4096
#define QKV_N    3072
#define PERSIST_CTAS 296   // 2 CTAs/SM * 148 SMs

// -------------------- scratch --------------------
__device__ float  g_resid[N_TOKENS * D_MODEL];
__device__ __half g_xh   [N_TOKENS * D_MODEL];
__device__ __half g_qkvh [N_TOKENS * QKV_N];
__device__ __half g_zh   [N_TOKENS * D_MODEL];
__device__ __half g_hh   [N_TOKENS * D_MLP];
__device__ __half g_wqkv [N_LAYERS * D_MODEL * QKV_N];
__device__ float  g_bqkv [N_LAYERS * QKV_N];
__device__ __half g_wo   [N_LAYERS * D_MODEL * D_MODEL];
__device__ __half g_win  [N_LAYERS * D_MODEL * D_MLP];
__device__ __half g_wout [N_LAYERS * D_MLP * D_MODEL];
__device__ __half g_wu   [D_MODEL * N_VOCAB_PAD];

#define WO_ELEMS  (N_LAYERS * D_MODEL * D_MODEL)
#define WIN_ELEMS (N_LAYERS * D_MODEL * D_MLP)
#define WOUT_ELEMS (N_LAYERS * D_MLP * D_MODEL)
#define FLAT3_ELEMS (WO_ELEMS + WIN_ELEMS + WOUT_ELEMS)

// -------------------- helpers --------------------
__device__ __forceinline__ float gelu_new(float x) {
  float u = 0.7978845608028654f * (x + 0.044715f * x * x * x);
  return 0.5f * x * (1.0f + tanhf(u));
}
__device__ __forceinline__ void ldsm_x4(uint32_t (&r)[4], uint32_t addr) {
  asm volatile("ldmatrix.sync.aligned.m8n8.x4.shared.b16 {%0,%1,%2,%3}, [%4];"
    : "=r"(r[0]), "=r"(r[1]), "=r"(r[2]), "=r"(r[3]) : "r"(addr));
}
__device__ __forceinline__ void ldsm_x4_t(uint32_t (&r)[4], uint32_t addr) {
  asm volatile("ldmatrix.sync.aligned.m8n8.x4.trans.shared.b16 {%0,%1,%2,%3}, [%4];"
    : "=r"(r[0]), "=r"(r[1]), "=r"(r[2]), "=r"(r[3]) : "r"(addr));
}
__device__ __forceinline__ void mma_f16(float (&c)[4], const uint32_t (&a)[4],
                                        const uint32_t b0, const uint32_t b1) {
  asm volatile("mma.sync.aligned.m16n8k16.row.col.f32.f16.f16.f32 "
    "{%0,%1,%2,%3}, {%4,%5,%6,%7}, {%8,%9}, {%0,%1,%2,%3};"
    : "+f"(c[0]), "+f"(c[1]), "+f"(c[2]), "+f"(c[3])
    : "r"(a[0]), "r"(a[1]), "r"(a[2]), "r"(a[3]), "r"(b0), "r"(b1));
}
__device__ __forceinline__ void cp_async16(uint32_t dst, const void* src) {
  asm volatile("cp.async.cg.shared.global [%0], [%1], 16;\n" :: "r"(dst), "l"(src));
}
__device__ __forceinline__ uint4 pack8(const float4 a, const float4 b) {
  __half2 h0 = __floats2half2_rn(a.x, a.y);
  __half2 h1 = __floats2half2_rn(a.z, a.w);
  __half2 h2 = __floats2half2_rn(b.x, b.y);
  __half2 h3 = __floats2half2_rn(b.z, b.w);
  uint4 r;
  r.x = *reinterpret_cast<uint32_t*>(&h0);
  r.y = *reinterpret_cast<uint32_t*>(&h1);
  r.z = *reinterpret_cast<uint32_t*>(&h2);
  r.w = *reinterpret_cast<uint32_t*>(&h3);
  return r;
}

// -------------------- weight conversion --------------------
__global__ __launch_bounds__(256) void conv_flat3(
    const float* __restrict__ wo_in, const float* __restrict__ win_in,
    const float* __restrict__ wout_in,
    __half* __restrict__ wo_out, __half* __restrict__ win_out,
    __half* __restrict__ wout_out) {
  size_t i8 = ((size_t)blockIdx.x * 256 + threadIdx.x) * 8;
  const float* src;
  __half* dst;
  size_t off;
  if (i8 < WO_ELEMS) {
    src = wo_in; dst = wo_out; off = i8;
  } else if (i8 < WO_ELEMS + WIN_ELEMS) {
    src = win_in; dst = win_out; off = i8 - WO_ELEMS;
  } else {
    src = wout_in; dst = wout_out; off = i8 - WO_ELEMS - WIN_ELEMS;
  }
  float4 a = *reinterpret_cast<const float4*>(src + off);
  float4 b = *reinterpret_cast<const float4*>(src + off + 4);
  *reinterpret_cast<uint4*>(dst + off) = pack8(a, b);
}
__global__ __launch_bounds__(256) void conv_qkv8(
    const float* __restrict__ WQ, const float* __restrict__ WK,
    const float* __restrict__ WV, __half* __restrict__ out) {
  size_t i8 = ((size_t)blockIdx.x * 256 + threadIdx.x) * 8;
  int n = (int)(i8 % QKV_N);
  size_t lk = i8 / QKV_N;
  int k = (int)(lk % D_MODEL);
  int l = (int)(lk / D_MODEL);
  int which = n >> 10, nn = n & 1023;
  int h = nn >> 6, dh = nn & 63;
  const float* W = (which == 0) ? WQ : ((which == 1) ? WK : WV);
  const float* src = W + (((size_t)l * N_HEADS + h) * D_MODEL + k) * D_HEAD + dh;
  float4 a = *reinterpret_cast<const float4*>(src);
  float4 b = *reinterpret_cast<const float4*>(src + 4);
  *reinterpret_cast<uint4*>(out + i8) = pack8(a, b);
}
__global__ __launch_bounds__(256) void conv_vocab8(
    const float* __restrict__ in, __half* __restrict__ out) {
  int k = blockIdx.y;
  int n = blockIdx.x * 2048 + threadIdx.x * 8;
  if (n >= N_VOCAB_PAD) return;
  const float* row = in + (size_t)k * N_VOCAB;
  float f[8];
#pragma unroll
  for (int u = 0; u < 8; u++) {
    int c = n + u;
    f[u] = (c < N_VOCAB) ? __ldg(row + c) : 0.f;
  }
  float4 a = make_float4(f[0], f[1], f[2], f[3]);
  float4 b = make_float4(f[4], f[5], f[6], f[7]);
  *reinterpret_cast<uint4*>(out + (size_t)k * N_VOCAB_PAD + n) = pack8(a, b);
}
__global__ __launch_bounds__(256) void pack_bias_qkv(
    const float* __restrict__ bq, const float* __restrict__ bk,
    const float* __restrict__ bv, float* __restrict__ out) {
  int i = blockIdx.x * 256 + threadIdx.x;
  int n = i % QKV_N, l = i / QKV_N;
  const float* s = (n < 1024) ? bq : ((n < 2048) ? bk : bv);
  out[i] = s[l * 1024 + (n & 1023)];
}

// -------------------- embedding --------------------
__global__ __launch_bounds__(256) void embed_kernel(
    const int* __restrict__ tok, const float* __restrict__ WE,
    const float* __restrict__ Wp, float* __restrict__ out) {
  int row = blockIdx.x;
  int s = row & (S_LEN - 1);
  int t = threadIdx.x;
  int token = tok[row];
  float4 e = reinterpret_cast<const float4*>(WE + (size_t)token * D_MODEL)[t];
  float4 p = reinterpret_cast<const float4*>(Wp + (size_t)s * D_MODEL)[t];
  float4 r;
  r.x = e.x + p.x; r.y = e.y + p.y; r.z = e.z + p.z; r.w = e.w + p.w;
  reinterpret_cast<float4*>(out + (size_t)row * D_MODEL)[t] = r;
}

// -------------------- layernorm --------------------
__global__ __launch_bounds__(256) void ln_kernel(
    const float* __restrict__ in, const float* __restrict__ w,
    const float* __restrict__ b, __half* __restrict__ out) {
  int row = blockIdx.x;
  int t = threadIdx.x;
  float4 v = reinterpret_cast<const float4*>(in + (size_t)row * D_MODEL)[t];
  float s  = v.x + v.y + v.z + v.w;
  float ss = v.x*v.x + v.y*v.y + v.z*v.z + v.w*v.w;
#pragma unroll
  for (int off = 16; off; off >>= 1) {
    s  += __shfl_xor_sync(0xffffffffu, s,  off);
    ss += __shfl_xor_sync(0xffffffffu, ss, off);
  }
  __shared__ float shs[8], shss[8];
  int wid = t >> 5;
  if ((t & 31) == 0) { shs[wid] = s; shss[wid] = ss; }
  __syncthreads();
  float tot = 0.f, tots = 0.f;
#pragma unroll
  for (int i = 0; i < 8; i++) { tot += shs[i]; tots += shss[i]; }
  float mean = tot * (1.0f / D_MODEL);
  float var  = tots * (1.0f / D_MODEL) - mean * mean;
  float rstd = rsqrtf(var + 1e-5f);
  float4 wv = reinterpret_cast<const float4*>(w)[t];
  float4 bv = reinterpret_cast<const float4*>(b)[t];
  float ox = (v.x - mean) * rstd * wv.x + bv.x;
  float oy = (v.y - mean) * rstd * wv.y + bv.y;
  float oz = (v.z - mean) * rstd * wv.z + bv.z;
  float ow = (v.w - mean) * rstd * wv.w + bv.w;
  __half2* o2 = reinterpret_cast<__half2*>(out + (size_t)row * D_MODEL);
  o2[2 * t]     = __floats2half2_rn(ox, oy);
  o2[2 * t + 1] = __floats2half2_rn(oz, ow);
}

// -------------------- FP16 tensor-core GEMM (persistent, 128x128) --------
#define KT        64
#define LDA_B     144
#define LDB_B     272
#define A_BYTES   (128 * LDA_B)
#define B_BYTES   (KT * LDB_B)
#define STAGE_B   (A_BYTES + B_BYTES)
#define NSTAGES   3
#define GEMM_SMEM (NSTAGES * STAGE_B)

template<bool GELU, bool ACCUM, bool OUTH, bool SWAP>
__global__ __launch_bounds__(256) void hgemm(
    const __half* __restrict__ A, const __half* __restrict__ B,
    const float* __restrict__ bias, void* __restrict__ Cv,
    int M, int K, int NB, int Nstore) {
  extern __shared__ __align__(16) char smem[];
  const uint32_t sm = (uint32_t)__cvta_generic_to_shared(smem);

  const int tid  = threadIdx.x;
  const int lane = tid & 31, warp = tid >> 5;
  const int wm = (warp >> 2) * 64;
  const int wn = (warp & 3) * 32;
  const int g = lane >> 2, t = lane & 3;
  const uint32_t laneRow = lane & 15, laneHi = lane >> 4;

  const int gridN = NB / 128, gridM = M / 128;
  const int total = gridM * gridN;
  const int NT = K / KT;
  float*  Cf = (float*)Cv;
  __half* Ch = (__half*)Cv;

  for (int tile = blockIdx.x; tile < total; tile += gridDim.x) {
    int bm, bn;
    if (SWAP) { bm = tile % gridM; bn = tile / gridM; }
    else      { bn = tile % gridN; bm = tile / gridN; }
    const int brow = bm * 128, bcol = bn * 128;

    float acc[16][4];
#pragma unroll
    for (int i = 0; i < 16; i++)
#pragma unroll
      for (int j = 0; j < 4; j++) acc[i][j] = 0.f;

    auto stage = [&](int tt) {
      const int k0 = tt * KT;
      const uint32_t sA = sm + (uint32_t)(tt % NSTAGES) * STAGE_B;
      const uint32_t sB = sA + A_BYTES;
      {
        int slot = tid;
#pragma unroll
        for (int i = 0; i < 4; i++) {
          int r = slot >> 3, ch = slot & 7;
          cp_async16(sA + (uint32_t)r * LDA_B + ch * 16,
                     A + (size_t)(brow + r) * K + k0 + ch * 8);
          slot += 256;
        }
      }
      {
        int slot = tid;
#pragma unroll
        for (int i = 0; i < 4; i++) {
          int r = slot >> 4, ch = slot & 15;
          cp_async16(sB + (uint32_t)r * LDB_B + ch * 16,
                     B + (size_t)(k0 + r) * NB + bcol + ch * 8);
          slot += 256;
        }
      }
      asm volatile("cp.async.commit_group;\n" ::: "memory");
    };

    stage(0);
    stage(1);

    for (int tt = 0; tt < NT; tt++) {
      if (tt + 1 < NT) {
        asm volatile("cp.async.wait_group 1;\n" ::: "memory");
      } else {
        asm volatile("cp.async.wait_group 0;\n" ::: "memory");
      }
      __syncthreads();
      if (tt + 2 < NT) stage(tt + 2);

      const uint32_t sA = sm + (uint32_t)(tt % NSTAGES) * STAGE_B;
      const uint32_t sB = sA + A_BYTES;

#pragma unroll
      for (int ik = 0; ik < 4; ik++) {
        uint32_t a[4][4];
#pragma unroll
        for (int im = 0; im < 4; im++)
          ldsm_x4(a[im], sA + (uint32_t)(wm + im * 16 + laneRow) * LDA_B
                            + ik * 32 + laneHi * 16);
        uint32_t b[4][2];
#pragma unroll
        for (int jp = 0; jp < 2; jp++) {
          uint32_t r[4];
          ldsm_x4_t(r, sB + (uint32_t)(ik * 16 + laneRow) * LDB_B
                          + (uint32_t)(wn + jp * 16 + laneHi * 8) * 2);
          b[2 * jp][0] = r[0]; b[2 * jp][1] = r[1];
          b[2 * jp + 1][0] = r[2]; b[2 * jp + 1][1] = r[3];
        }
#pragma unroll
        for (int im = 0; im < 4; im++)
#pragma unroll
          for (int jn = 0; jn < 4; jn++)
            mma_f16(acc[im * 4 + jn], a[im], b[jn][0], b[jn][1]);
      }
      __syncthreads();
    }

    // epilogue (register-only; smem free for next tile's staging)
#pragma unroll
    for (int im = 0; im < 4; im++) {
#pragma unroll
      for (int jn = 0; jn < 4; jn++) {
        const float* c = acc[im * 4 + jn];
        int r0 = brow + wm + im * 16 + g;
        int c0 = bcol + wn + jn * 8 + 2 * t;
#pragma unroll
        for (int u = 0; u < 4; u++) {
          int r = r0 + (u >> 1) * 8;
          int cc = c0 + (u & 1);
          if (cc < Nstore) {
            float val = c[u] + bias[cc];
            if (GELU) val = gelu_new(val);
            size_t idx = (size_t)r * Nstore + cc;
            if (OUTH) {
              Ch[idx] = __float2half(val);
            } else {
              if (ACCUM) val += Cf[idx];
              Cf[idx] = val;
            }
          }
        }
      }
    }
  }
}

// -------------------- tensor-core flash attention --------------------
#define ATT_LD 144
__global__ __launch_bounds__(128) void attn_tc(
    const __half* __restrict__ qkv, __half* __restrict__ z) {
  const int b = blockIdx.z, h = blockIdx.y;
  const int q0 = (gridDim.x - 1 - blockIdx.x) * 64;
  const int tid = threadIdx.x;
  const int warp = tid >> 5, lane = tid & 31;
  const int g = lane >> 2, t = lane & 3;

  __shared__ __align__(16) __half sQ[64 * 72];
  __shared__ __align__(16) __half sK[2][64 * 72];
  __shared__ __align__(16) __half sV[2][64 * 72];
  const uint32_t qb = (uint32_t)__cvta_generic_to_shared(sQ);
  const uint32_t kb0 = (uint32_t)__cvta_generic_to_shared(sK[0]);
  const uint32_t kb1 = (uint32_t)__cvta_generic_to_shared(sK[1]);
  const uint32_t vb0 = (uint32_t)__cvta_generic_to_shared(sV[0]);
  const uint32_t vb1 = (uint32_t)__cvta_generic_to_shared(sV[1]);

  for (int slot = tid; slot < 512; slot += 128) {
    int r = slot >> 3, c = slot & 7;
    *reinterpret_cast<uint4*>(&sQ[r * 72 + c * 8]) =
      *reinterpret_cast<const uint4*>(
        qkv + (size_t)(b * S_LEN + q0 + r) * QKV_N + h * D_HEAD + c * 8);
  }
  __syncthreads();

  uint32_t qf[4][4];
#pragma unroll
  for (int ik = 0; ik < 4; ik++)
    ldsm_x4(qf[ik], qb + (uint32_t)(warp * 16 + (lane & 15)) * ATT_LD
                       + ik * 32 + (lane >> 4) * 16);

  const int row0 = q0 + warp * 16 + g;
  const int row1 = row0 + 8;

  float m0 = -INFINITY, m1 = -INFINITY, l0 = 0.f, l1 = 0.f;
  float oacc[8][4];
#pragma unroll
  for (int i = 0; i < 8; i++)
#pragma unroll
    for (int j = 0; j < 4; j++) oacc[i][j] = 0.f;

  const int ntiles = (q0 >> 6) + 1;

  auto stageKV = [&](int tile) {
    const int kt = tile * 64;
    const uint32_t kd = (tile & 1) ? kb1 : kb0;
    const uint32_t vd = (tile & 1) ? vb1 : vb0;
    for (int slot = tid; slot < 512; slot += 128) {
      int r = slot >> 3, c = slot & 7;
      const __half* src = qkv + (size_t)(b * S_LEN + kt + r) * QKV_N
                              + 1024 + h * D_HEAD + c * 8;
      cp_async16(kd + (uint32_t)r * ATT_LD + c * 16, src);
      cp_async16(vd + (uint32_t)r * ATT_LD + c * 16, src + 1024);
    }
    asm volatile("cp.async.commit_group;\n" ::: "memory");
  };

  stageKV(0);

  for (int tile = 0; tile < ntiles; tile++) {
    asm volatile("cp.async.wait_group 0;\n" ::: "memory");
    __syncthreads();
    if (tile + 1 < ntiles) stageKV(tile + 1);

    const uint32_t kd = (tile & 1) ? kb1 : kb0;
    const uint32_t vd = (tile & 1) ? vb1 : vb0;
    const int kt = tile * 64;

    float sacc[8][4];
#pragma unroll
    for (int j = 0; j < 8; j++) {
#pragma unroll
      for (int u = 0; u < 4; u++) sacc[j][u] = 0.f;
      uint32_t bk0[4], bk1[4];
      uint32_t base = kd + (uint32_t)(j * 8 + (lane & 7)) * ATT_LD + (lane >> 3) * 16;
      ldsm_x4(bk0, base);
      ldsm_x4(bk1, base + 64);
      mma_f16(sacc[j], qf[0], bk0[0], bk0[1]);
      mma_f16(sacc[j], qf[1], bk0[2], bk0[3]);
      mma_f16(sacc[j], qf[2], bk1[0], bk1[1]);
      mma_f16(sacc[j], qf[3], bk1[2], bk1[3]);
    }

    float tmx0 = -1e30f, tmx1 = -1e30f;
#pragma unroll
    for (int j = 0; j < 8; j++) {
      int kbase = kt + j * 8 + 2 * t;
      sacc[j][0] = (kbase     <= row0) ? sacc[j][0] * 0.125f : -1e30f;
      sacc[j][1] = (kbase + 1 <= row0) ? sacc[j][1] * 0.125f : -1e30f;
      sacc[j][2] = (kbase     <= row1) ? sacc[j][2] * 0.125f : -1e30f;
      sacc[j][3] = (kbase + 1 <= row1) ? sacc[j][3] * 0.125f : -1e30f;
      tmx0 = fmaxf(tmx0, fmaxf(sacc[j][0], sacc[j][1]));
      tmx1 = fmaxf(tmx1, fmaxf(sacc[j][2], sacc[j][3]));
    }
#pragma unroll
    for (int off = 1; off <= 2; off <<= 1) {
      tmx0 = fmaxf(tmx0, __shfl_xor_sync(0xffffffffu, tmx0, off));
      tmx1 = fmaxf(tmx1, __shfl_xor_sync(0xffffffffu, tmx1, off));
    }
    float mn0 = fmaxf(m0, tmx0), mn1 = fmaxf(m1, tmx1);
    float corr0 = __expf(m0 - mn0), corr1 = __expf(m1 - mn1);
    m0 = mn0; m1 = mn1;

    uint32_t pf[8][2];
    float sum0 = 0.f, sum1 = 0.f;
#pragma unroll
    for (int j = 0; j < 8; j++) {
      float p0 = __expf(sacc[j][0] - mn0);
      float p1 = __expf(sacc[j][1] - mn0);
      float p2 = __expf(sacc[j][2] - mn1);
      float p3 = __expf(sacc[j][3] - mn1);
      sum0 += p0 + p1; sum1 += p2 + p3;
      __half2 h01 = __floats2half2_rn(p0, p1);
      __half2 h23 = __floats2half2_rn(p2, p3);
      pf[j][0] = *reinterpret_cast<uint32_t*>(&h01);
      pf[j][1] = *reinterpret_cast<uint32_t*>(&h23);
    }
#pragma unroll
    for (int off = 1; off <= 2; off <<= 1) {
      sum0 += __shfl_xor_sync(0xffffffffu, sum0, off);
      sum1 += __shfl_xor_sync(0xffffffffu, sum1, off);
    }
    l0 = l0 * corr0 + sum0;
    l1 = l1 * corr1 + sum1;
#pragma unroll
    for (int np = 0; np < 8; np++) {
      oacc[np][0] *= corr0; oacc[np][1] *= corr0;
      oacc[np][2] *= corr1; oacc[np][3] *= corr1;
    }

#pragma unroll
    for (int kk = 0; kk < 4; kk++) {
      uint32_t a[4] = { pf[2 * kk][0], pf[2 * kk][1],
                        pf[2 * kk + 1][0], pf[2 * kk + 1][1] };
#pragma unroll
      for (int np = 0; np < 4; np++) {
        uint32_t r[4];
        ldsm_x4_t(r, vd + (uint32_t)(kk * 16 + (lane & 15)) * ATT_LD
                        + np * 32 + (lane >> 4) * 16);
        mma_f16(oacc[2 * np], a, r[0], r[1]);
        mma_f16(oacc[2 * np + 1], a, r[2], r[3]);
      }
    }
    __syncthreads();
  }

  const float inv0 = 1.0f / l0, inv1 = 1.0f / l1;
#pragma unroll
  for (int np = 0; np < 8; np++) {
    int col = h * D_HEAD + np * 8 + 2 * t;
    __half2 lo = __floats2half2_rn(oacc[np][0] * inv0, oacc[np][1] * inv0);
    __half2 hi = __floats2half2_rn(oacc[np][2] * inv1, oacc[np][3] * inv1);
    *reinterpret_cast<__half2*>(&z[(size_t)(b * S_LEN + row0) * D_MODEL + col]) = lo;
    *reinterpret_cast<__half2*>(&z[(size_t)(b * S_LEN + row1) * D_MODEL + col]) = hi;
  }
}

// -------------------- driver --------------------
template<bool GELU, bool ACCUM, bool OUTH, bool SWAP>
static void launch_hgemm(const __half* A, const __half* B, const float* bias,
                         void* C, int M, int K, int NB, int Nstore) {
  cudaFuncSetAttribute(hgemm<GELU, ACCUM, OUTH, SWAP>,
                       cudaFuncAttributeMaxDynamicSharedMemorySize, GEMM_SMEM);
  int total = (NB / 128) * (M / 128);
  int nblk = total < PERSIST_CTAS ? total : PERSIST_CTAS;
  hgemm<GELU, ACCUM, OUTH, SWAP><<<nblk, 256, GEMM_SMEM>>>(A, B, bias, C, M, K, NB, Nstore);
}

extern "C" void kernel_launch(void* const* d_in, const int* in_sizes, int n_in,
                              void* d_out, int out_size) {
  const int*   tokens = (const int*)  d_in[0];
  const float* W_E    = (const float*)d_in[1];
  const float* W_pos  = (const float*)d_in[2];
  const float* ln1_w  = (const float*)d_in[3];
  const float* ln1_b  = (const float*)d_in[4];
  const float* W_Q    = (const float*)d_in[5];
  const float* b_Q    = (const float*)d_in[6];
  const float* W_K    = (const float*)d_in[7];
  const float* b_K    = (const float*)d_in[8];
  const float* W_V    = (const float*)d_in[9];
  const float* b_V    = (const float*)d_in[10];
  const float* W_O    = (const float*)d_in[11];
  const float* b_O    = (const float*)d_in[12];
  const float* ln2_w  = (const float*)d_in[13];
  const float* ln2_b  = (const float*)d_in[14];
  const float* W_in   = (const float*)d_in[15];
  const float* b_in   = (const float*)d_in[16];
  const float* W_out  = (const float*)d_in[17];
  const float* b_out  = (const float*)d_in[18];
  const float* lnf_w  = (const float*)d_in[19];
  const float* lnf_b  = (const float*)d_in[20];
  const float* W_U    = (const float*)d_in[21];
  const float* b_U    = (const float*)d_in[22];
  float* out = (float*)d_out;

  float *resid, *bqkv;
  __half *xh, *qkvh, *zh, *hh, *wqkv, *wo, *win, *wout, *wu;
  cudaGetSymbolAddress((void**)&resid, g_resid);
  cudaGetSymbolAddress((void**)&xh,    g_xh);
  cudaGetSymbolAddress((void**)&qkvh,  g_qkvh);
  cudaGetSymbolAddress((void**)&zh,    g_zh);
  cudaGetSymbolAddress((void**)&hh,    g_hh);
  cudaGetSymbolAddress((void**)&wqkv,  g_wqkv);
  cudaGetSymbolAddress((void**)&bqkv,  g_bqkv);
  cudaGetSymbolAddress((void**)&wo,    g_wo);
  cudaGetSymbolAddress((void**)&win,   g_win);
  cudaGetSymbolAddress((void**)&wout,  g_wout);
  cudaGetSymbolAddress((void**)&wu,    g_wu);

  conv_qkv8<<<(N_LAYERS * D_MODEL * QKV_N) / 2048, 256>>>(W_Q, W_K, W_V, wqkv);
  pack_bias_qkv<<<(N_LAYERS * QKV_N) / 256, 256>>>(b_Q, b_K, b_V, bqkv);
  conv_flat3<<<FLAT3_ELEMS / 2048, 256>>>(W_O, W_in, W_out, wo, win, wout);
  embed_kernel<<<N_TOKENS, 256>>>(tokens, W_E, W_pos, resid);

  dim3 gA(S_LEN / 64, N_HEADS, 2);

  for (int l = 0; l < N_LAYERS; l++) {
    size_t w1 = (size_t)l * D_MODEL * D_MODEL;
    size_t w2 = (size_t)l * D_MODEL * D_MLP;
    const float* l1w = ln1_w + (size_t)l * D_MODEL;
    const float* l1b = ln1_b + (size_t)l * D_MODEL;
    const float* l2w = ln2_w + (size_t)l * D_MODEL;
    const float* l2b = ln2_b + (size_t)l * D_MODEL;

    ln_kernel<<<N_TOKENS, 256>>>(resid, l1w, l1b, xh);
    launch_hgemm<false, false, true, false>(xh, wqkv + (size_t)l * D_MODEL * QKV_N,
                                            bqkv + (size_t)l * QKV_N, qkvh,
                                            N_TOKENS, D_MODEL, QKV_N, QKV_N);
    attn_tc<<<gA, 128>>>(qkvh, zh);
    launch_hgemm<false, true, false, false>(zh, wo + w1, b_O + (size_t)l * D_MODEL, resid,
                                            N_TOKENS, D_MODEL, D_MODEL, D_MODEL);
    ln_kernel<<<N_TOKENS, 256>>>(resid, l2w, l2b, xh);
    launch_hgemm<true, false, true, false>(xh, win + w2, b_in + (size_t)l * D_MLP, hh,
                                           N_TOKENS, D_MODEL, D_MLP, D_MLP);
    launch_hgemm<false, true, false, false>(hh, wout + w2, b_out + (size_t)l * D_MODEL, resid,
                                            N_TOKENS, D_MLP, D_MODEL, D_MODEL);
  }

  ln_kernel<<<N_TOKENS, 256>>>(resid, lnf_w, lnf_b, xh);
  {
    dim3 gv((N_VOCAB_PAD + 2047) / 2048, D_MODEL);
    conv_vocab8<<<gv, 256>>>(W_U, wu);
  }
  launch_hgemm<false, false, false, true>(xh, wu, b_U, out,
                                          N_TOKENS, D_MODEL, N_VOCAB_PAD, N_VOCAB);
}

// round 14
// speedup vs baseline: 1.0896x; 1.0477x over previous
#include <cuda_runtime.h>
#include <cuda_fp16.h>
#include <cstdint>
#include <math.h>

#define S_LEN    2048
#define D_MODEL  1024
#define N_HEADS  16
#define D_HEAD   64
#define D_MLP    4096
#define N_LAYERS 4
#define N_VOCAB  50257
#define N_VOCAB_PAD 50432
#define N_TOKENS 4096
#define QKV_N    3072

// -------------------- scratch --------------------
__device__ float  g_resid[N_TOKENS * D_MODEL];
__device__ __half g_xh   [N_TOKENS * D_MODEL];
__device__ __half g_qkvh [N_TOKENS * QKV_N];
__device__ __half g_zh   [N_TOKENS * D_MODEL];
__device__ __half g_hh   [N_TOKENS * D_MLP];
__device__ __half g_wqkv [N_LAYERS * D_MODEL * QKV_N];
__device__ float  g_bqkv [N_LAYERS * QKV_N];
__device__ __half g_wo   [N_LAYERS * D_MODEL * D_MODEL];
__device__ __half g_win  [N_LAYERS * D_MODEL * D_MLP];
__device__ __half g_wout [N_LAYERS * D_MLP * D_MODEL];
__device__ __half g_wu   [D_MODEL * N_VOCAB_PAD];

// -------------------- helpers --------------------
__device__ __forceinline__ float gelu_new(float x) {
  float u = 0.7978845608028654f * (x + 0.044715f * x * x * x);
  return 0.5f * x * (1.0f + tanhf(u));
}
__device__ __forceinline__ void ldsm_x4(uint32_t (&r)[4], uint32_t addr) {
  asm volatile("ldmatrix.sync.aligned.m8n8.x4.shared.b16 {%0,%1,%2,%3}, [%4];"
    : "=r"(r[0]), "=r"(r[1]), "=r"(r[2]), "=r"(r[3]) : "r"(addr));
}
__device__ __forceinline__ void ldsm_x4_t(uint32_t (&r)[4], uint32_t addr) {
  asm volatile("ldmatrix.sync.aligned.m8n8.x4.trans.shared.b16 {%0,%1,%2,%3}, [%4];"
    : "=r"(r[0]), "=r"(r[1]), "=r"(r[2]), "=r"(r[3]) : "r"(addr));
}
__device__ __forceinline__ void mma_f16(float (&c)[4], const uint32_t (&a)[4],
                                        const uint32_t b0, const uint32_t b1) {
  asm volatile("mma.sync.aligned.m16n8k16.row.col.f32.f16.f16.f32 "
    "{%0,%1,%2,%3}, {%4,%5,%6,%7}, {%8,%9}, {%0,%1,%2,%3};"
    : "+f"(c[0]), "+f"(c[1]), "+f"(c[2]), "+f"(c[3])
    : "r"(a[0]), "r"(a[1]), "r"(a[2]), "r"(a[3]), "r"(b0), "r"(b1));
}
__device__ __forceinline__ void cp_async16(uint32_t dst, const void* src) {
  asm volatile("cp.async.cg.shared.global [%0], [%1], 16;\n" :: "r"(dst), "l"(src));
}
__device__ __forceinline__ uint4 pack8(const float4 a, const float4 b) {
  __half2 h0 = __floats2half2_rn(a.x, a.y);
  __half2 h1 = __floats2half2_rn(a.z, a.w);
  __half2 h2 = __floats2half2_rn(b.x, b.y);
  __half2 h3 = __floats2half2_rn(b.z, b.w);
  uint4 r;
  r.x = *reinterpret_cast<uint32_t*>(&h0);
  r.y = *reinterpret_cast<uint32_t*>(&h1);
  r.z = *reinterpret_cast<uint32_t*>(&h2);
  r.w = *reinterpret_cast<uint32_t*>(&h3);
  return r;
}

// -------------------- weight conversion --------------------
__global__ __launch_bounds__(256) void conv_flat8(
    const float* __restrict__ in, __half* __restrict__ out) {
  size_t i8 = ((size_t)blockIdx.x * 256 + threadIdx.x) * 8;
  float4 a = *reinterpret_cast<const float4*>(in + i8);
  float4 b = *reinterpret_cast<const float4*>(in + i8 + 4);
  *reinterpret_cast<uint4*>(out + i8) = pack8(a, b);
}
__global__ __launch_bounds__(256) void conv_qkv8(
    const float* __restrict__ WQ, const float* __restrict__ WK,
    const float* __restrict__ WV, __half* __restrict__ out) {
  size_t i8 = ((size_t)blockIdx.x * 256 + threadIdx.x) * 8;
  int n = (int)(i8 % QKV_N);
  size_t lk = i8 / QKV_N;
  int k = (int)(lk % D_MODEL);
  int l = (int)(lk / D_MODEL);
  int which = n >> 10, nn = n & 1023;
  int h = nn >> 6, dh = nn & 63;
  const float* W = (which == 0) ? WQ : ((which == 1) ? WK : WV);
  const float* src = W + (((size_t)l * N_HEADS + h) * D_MODEL + k) * D_HEAD + dh;
  float4 a = *reinterpret_cast<const float4*>(src);
  float4 b = *reinterpret_cast<const float4*>(src + 4);
  *reinterpret_cast<uint4*>(out + i8) = pack8(a, b);
}
__global__ __launch_bounds__(256) void conv_vocab8(
    const float* __restrict__ in, __half* __restrict__ out) {
  int k = blockIdx.y;
  int n = blockIdx.x * 2048 + threadIdx.x * 8;
  if (n >= N_VOCAB_PAD) return;
  const float* row = in + (size_t)k * N_VOCAB;
  float f[8];
#pragma unroll
  for (int u = 0; u < 8; u++) {
    int c = n + u;
    f[u] = (c < N_VOCAB) ? __ldg(row + c) : 0.f;
  }
  float4 a = make_float4(f[0], f[1], f[2], f[3]);
  float4 b = make_float4(f[4], f[5], f[6], f[7]);
  *reinterpret_cast<uint4*>(out + (size_t)k * N_VOCAB_PAD + n) = pack8(a, b);
}
__global__ __launch_bounds__(256) void pack_bias_qkv(
    const float* __restrict__ bq, const float* __restrict__ bk,
    const float* __restrict__ bv, float* __restrict__ out) {
  int i = blockIdx.x * 256 + threadIdx.x;
  int n = i % QKV_N, l = i / QKV_N;
  const float* s = (n < 1024) ? bq : ((n < 2048) ? bk : bv);
  out[i] = s[l * 1024 + (n & 1023)];
}

// -------------------- embedding (128 thr, 2 indep float4/thread) ---------
__global__ __launch_bounds__(128) void embed_kernel(
    const int* __restrict__ tok, const float* __restrict__ WE,
    const float* __restrict__ Wp, float* __restrict__ out) {
  int row = blockIdx.x;
  int s = row & (S_LEN - 1);
  int t = threadIdx.x;
  int token = tok[row];
  const float4* we = reinterpret_cast<const float4*>(WE + (size_t)token * D_MODEL);
  const float4* wp = reinterpret_cast<const float4*>(Wp + (size_t)s * D_MODEL);
  float4 e0 = we[t], e1 = we[t + 128];
  float4 p0 = wp[t], p1 = wp[t + 128];
  float4 r0, r1;
  r0.x = e0.x + p0.x; r0.y = e0.y + p0.y; r0.z = e0.z + p0.z; r0.w = e0.w + p0.w;
  r1.x = e1.x + p1.x; r1.y = e1.y + p1.y; r1.z = e1.z + p1.z; r1.w = e1.w + p1.w;
  float4* o = reinterpret_cast<float4*>(out + (size_t)row * D_MODEL);
  o[t] = r0;
  o[t + 128] = r1;
}

// -------------------- layernorm (128 thr, 2 indep float4/thread) ---------
__global__ __launch_bounds__(128) void ln_kernel(
    const float* __restrict__ in, const float* __restrict__ w,
    const float* __restrict__ b, __half* __restrict__ out) {
  int row = blockIdx.x;
  int t = threadIdx.x;    // 0..127
  const float4* ip = reinterpret_cast<const float4*>(in + (size_t)row * D_MODEL);
  float4 v0 = ip[t], v1 = ip[t + 128];
  float s  = v0.x + v0.y + v0.z + v0.w + v1.x + v1.y + v1.z + v1.w;
  float ss = v0.x*v0.x + v0.y*v0.y + v0.z*v0.z + v0.w*v0.w
           + v1.x*v1.x + v1.y*v1.y + v1.z*v1.z + v1.w*v1.w;
#pragma unroll
  for (int off = 16; off; off >>= 1) {
    s  += __shfl_xor_sync(0xffffffffu, s,  off);
    ss += __shfl_xor_sync(0xffffffffu, ss, off);
  }
  __shared__ float shs[4], shss[4];
  int wid = t >> 5;
  if ((t & 31) == 0) { shs[wid] = s; shss[wid] = ss; }
  __syncthreads();
  float tot  = shs[0] + shs[1] + shs[2] + shs[3];
  float tots = shss[0] + shss[1] + shss[2] + shss[3];
  float mean = tot * (1.0f / D_MODEL);
  float var  = tots * (1.0f / D_MODEL) - mean * mean;
  float rstd = rsqrtf(var + 1e-5f);
  const float4* wp = reinterpret_cast<const float4*>(w);
  const float4* bp = reinterpret_cast<const float4*>(b);
  float4 w0 = wp[t], w1 = wp[t + 128];
  float4 b0 = bp[t], b1 = bp[t + 128];
  __half2* o2 = reinterpret_cast<__half2*>(out + (size_t)row * D_MODEL);
  o2[2 * t]     = __floats2half2_rn((v0.x - mean) * rstd * w0.x + b0.x,
                                    (v0.y - mean) * rstd * w0.y + b0.y);
  o2[2 * t + 1] = __floats2half2_rn((v0.z - mean) * rstd * w0.z + b0.z,
                                    (v0.w - mean) * rstd * w0.w + b0.w);
  o2[2 * (t + 128)]     = __floats2half2_rn((v1.x - mean) * rstd * w1.x + b1.x,
                                            (v1.y - mean) * rstd * w1.y + b1.y);
  o2[2 * (t + 128) + 1] = __floats2half2_rn((v1.z - mean) * rstd * w1.z + b1.z,
                                            (v1.w - mean) * rstd * w1.w + b1.w);
}

// -------------------- FP16 tensor-core GEMM (128x128, warp 64x32) --------
#define KT        64
#define LDA_B     144
#define LDB_B     272
#define A_BYTES   (128 * LDA_B)
#define B_BYTES   (KT * LDB_B)
#define STAGE_B   (A_BYTES + B_BYTES)
#define NSTAGES   3
#define GEMM_SMEM (NSTAGES * STAGE_B)

template<bool GELU, bool ACCUM, bool OUTH, bool SWAP>
__global__ __launch_bounds__(256) void hgemm(
    const __half* __restrict__ A, const __half* __restrict__ B,
    const float* __restrict__ bias, void* __restrict__ Cv,
    int M, int K, int NB, int Nstore) {
  extern __shared__ __align__(16) char smem[];
  const uint32_t sm = (uint32_t)__cvta_generic_to_shared(smem);

  const int tid  = threadIdx.x;
  const int lane = tid & 31, warp = tid >> 5;
  const int wm = (warp >> 2) * 64;
  const int wn = (warp & 3) * 32;
  const int g = lane >> 2, t = lane & 3;
  const int brow = (SWAP ? blockIdx.x : blockIdx.y) * 128;
  const int bcol = (SWAP ? blockIdx.y : blockIdx.x) * 128;
  const uint32_t laneRow = lane & 15, laneHi = lane >> 4;

  float acc[16][4];
#pragma unroll
  for (int i = 0; i < 16; i++)
#pragma unroll
    for (int j = 0; j < 4; j++) acc[i][j] = 0.f;

  const int NT = K / KT;

  auto stage = [&](int tt) {
    const int k0 = tt * KT;
    const uint32_t sA = sm + (uint32_t)(tt % NSTAGES) * STAGE_B;
    const uint32_t sB = sA + A_BYTES;
    {
      int slot = tid;
#pragma unroll
      for (int i = 0; i < 4; i++) {
        int r = slot >> 3, ch = slot & 7;
        cp_async16(sA + (uint32_t)r * LDA_B + ch * 16,
                   A + (size_t)(brow + r) * K + k0 + ch * 8);
        slot += 256;
      }
    }
    {
      int slot = tid;
#pragma unroll
      for (int i = 0; i < 4; i++) {
        int r = slot >> 4, ch = slot & 15;
        cp_async16(sB + (uint32_t)r * LDB_B + ch * 16,
                   B + (size_t)(k0 + r) * NB + bcol + ch * 8);
        slot += 256;
      }
    }
    asm volatile("cp.async.commit_group;\n" ::: "memory");
  };

  stage(0);
  if (NT > 1) stage(1);

  for (int tt = 0; tt < NT; tt++) {
    if (tt + 1 < NT) {
      asm volatile("cp.async.wait_group 1;\n" ::: "memory");
    } else {
      asm volatile("cp.async.wait_group 0;\n" ::: "memory");
    }
    __syncthreads();
    if (tt + 2 < NT) stage(tt + 2);

    const uint32_t sA = sm + (uint32_t)(tt % NSTAGES) * STAGE_B;
    const uint32_t sB = sA + A_BYTES;

#pragma unroll
    for (int ik = 0; ik < 4; ik++) {
      uint32_t a[4][4];
#pragma unroll
      for (int im = 0; im < 4; im++)
        ldsm_x4(a[im], sA + (uint32_t)(wm + im * 16 + laneRow) * LDA_B
                          + ik * 32 + laneHi * 16);
      uint32_t b[4][2];
#pragma unroll
      for (int jp = 0; jp < 2; jp++) {
        uint32_t r[4];
        ldsm_x4_t(r, sB + (uint32_t)(ik * 16 + laneRow) * LDB_B
                        + (uint32_t)(wn + jp * 16 + laneHi * 8) * 2);
        b[2 * jp][0] = r[0]; b[2 * jp][1] = r[1];
        b[2 * jp + 1][0] = r[2]; b[2 * jp + 1][1] = r[3];
      }
#pragma unroll
      for (int im = 0; im < 4; im++)
#pragma unroll
        for (int jn = 0; jn < 4; jn++)
          mma_f16(acc[im * 4 + jn], a[im], b[jn][0], b[jn][1]);
    }
    __syncthreads();
  }

  float*  Cf = (float*)Cv;
  __half* Ch = (__half*)Cv;
#pragma unroll
  for (int im = 0; im < 4; im++) {
#pragma unroll
    for (int jn = 0; jn < 4; jn++) {
      const float* c = acc[im * 4 + jn];
      int r0 = brow + wm + im * 16 + g;
      int c0 = bcol + wn + jn * 8 + 2 * t;
#pragma unroll
      for (int u = 0; u < 4; u++) {
        int r = r0 + (u >> 1) * 8;
        int cc = c0 + (u & 1);
        if (cc < Nstore) {
          float val = c[u] + bias[cc];
          if (GELU) val = gelu_new(val);
          size_t idx = (size_t)r * Nstore + cc;
          if (OUTH) {
            Ch[idx] = __float2half(val);
          } else {
            if (ACCUM) val += Cf[idx];
            Cf[idx] = val;
          }
        }
      }
    }
  }
}

// -------------------- tensor-core flash attention --------------------
#define ATT_LD 144
__global__ __launch_bounds__(128) void attn_tc(
    const __half* __restrict__ qkv, __half* __restrict__ z) {
  const int b = blockIdx.z, h = blockIdx.y;
  const int q0 = (gridDim.x - 1 - blockIdx.x) * 64;
  const int tid = threadIdx.x;
  const int warp = tid >> 5, lane = tid & 31;
  const int g = lane >> 2, t = lane & 3;

  __shared__ __align__(16) __half sQ[64 * 72];
  __shared__ __align__(16) __half sK[2][64 * 72];
  __shared__ __align__(16) __half sV[2][64 * 72];
  const uint32_t qb = (uint32_t)__cvta_generic_to_shared(sQ);
  const uint32_t kb0 = (uint32_t)__cvta_generic_to_shared(sK[0]);
  const uint32_t kb1 = (uint32_t)__cvta_generic_to_shared(sK[1]);
  const uint32_t vb0 = (uint32_t)__cvta_generic_to_shared(sV[0]);
  const uint32_t vb1 = (uint32_t)__cvta_generic_to_shared(sV[1]);

  for (int slot = tid; slot < 512; slot += 128) {
    int r = slot >> 3, c = slot & 7;
    *reinterpret_cast<uint4*>(&sQ[r * 72 + c * 8]) =
      *reinterpret_cast<const uint4*>(
        qkv + (size_t)(b * S_LEN + q0 + r) * QKV_N + h * D_HEAD + c * 8);
  }
  __syncthreads();

  uint32_t qf[4][4];
#pragma unroll
  for (int ik = 0; ik < 4; ik++)
    ldsm_x4(qf[ik], qb + (uint32_t)(warp * 16 + (lane & 15)) * ATT_LD
                       + ik * 32 + (lane >> 4) * 16);

  const int row0 = q0 + warp * 16 + g;
  const int row1 = row0 + 8;

  float m0 = -INFINITY, m1 = -INFINITY, l0 = 0.f, l1 = 0.f;
  float oacc[8][4];
#pragma unroll
  for (int i = 0; i < 8; i++)
#pragma unroll
    for (int j = 0; j < 4; j++) oacc[i][j] = 0.f;

  const int ntiles = (q0 >> 6) + 1;

  auto stageKV = [&](int tile) {
    const int kt = tile * 64;
    const uint32_t kd = (tile & 1) ? kb1 : kb0;
    const uint32_t vd = (tile & 1) ? vb1 : vb0;
    for (int slot = tid; slot < 512; slot += 128) {
      int r = slot >> 3, c = slot & 7;
      const __half* src = qkv + (size_t)(b * S_LEN + kt + r) * QKV_N
                              + 1024 + h * D_HEAD + c * 8;
      cp_async16(kd + (uint32_t)r * ATT_LD + c * 16, src);
      cp_async16(vd + (uint32_t)r * ATT_LD + c * 16, src + 1024);
    }
    asm volatile("cp.async.commit_group;\n" ::: "memory");
  };

  stageKV(0);

  for (int tile = 0; tile < ntiles; tile++) {
    asm volatile("cp.async.wait_group 0;\n" ::: "memory");
    __syncthreads();
    if (tile + 1 < ntiles) stageKV(tile + 1);

    const uint32_t kd = (tile & 1) ? kb1 : kb0;
    const uint32_t vd = (tile & 1) ? vb1 : vb0;
    const int kt = tile * 64;

    float sacc[8][4];
#pragma unroll
    for (int j = 0; j < 8; j++) {
#pragma unroll
      for (int u = 0; u < 4; u++) sacc[j][u] = 0.f;
      uint32_t bk0[4], bk1[4];
      uint32_t base = kd + (uint32_t)(j * 8 + (lane & 7)) * ATT_LD + (lane >> 3) * 16;
      ldsm_x4(bk0, base);
      ldsm_x4(bk1, base + 64);
      mma_f16(sacc[j], qf[0], bk0[0], bk0[1]);
      mma_f16(sacc[j], qf[1], bk0[2], bk0[3]);
      mma_f16(sacc[j], qf[2], bk1[0], bk1[1]);
      mma_f16(sacc[j], qf[3], bk1[2], bk1[3]);
    }

    float tmx0 = -1e30f, tmx1 = -1e30f;
#pragma unroll
    for (int j = 0; j < 8; j++) {
      int kbase = kt + j * 8 + 2 * t;
      sacc[j][0] = (kbase     <= row0) ? sacc[j][0] * 0.125f : -1e30f;
      sacc[j][1] = (kbase + 1 <= row0) ? sacc[j][1] * 0.125f : -1e30f;
      sacc[j][2] = (kbase     <= row1) ? sacc[j][2] * 0.125f : -1e30f;
      sacc[j][3] = (kbase + 1 <= row1) ? sacc[j][3] * 0.125f : -1e30f;
      tmx0 = fmaxf(tmx0, fmaxf(sacc[j][0], sacc[j][1]));
      tmx1 = fmaxf(tmx1, fmaxf(sacc[j][2], sacc[j][3]));
    }
#pragma unroll
    for (int off = 1; off <= 2; off <<= 1) {
      tmx0 = fmaxf(tmx0, __shfl_xor_sync(0xffffffffu, tmx0, off));
      tmx1 = fmaxf(tmx1, __shfl_xor_sync(0xffffffffu, tmx1, off));
    }
    float mn0 = fmaxf(m0, tmx0), mn1 = fmaxf(m1, tmx1);
    float corr0 = __expf(m0 - mn0), corr1 = __expf(m1 - mn1);
    m0 = mn0; m1 = mn1;

    uint32_t pf[8][2];
    float sum0 = 0.f, sum1 = 0.f;
#pragma unroll
    for (int j = 0; j < 8; j++) {
      float p0 = __expf(sacc[j][0] - mn0);
      float p1 = __expf(sacc[j][1] - mn0);
      float p2 = __expf(sacc[j][2] - mn1);
      float p3 = __expf(sacc[j][3] - mn1);
      sum0 += p0 + p1; sum1 += p2 + p3;
      __half2 h01 = __floats2half2_rn(p0, p1);
      __half2 h23 = __floats2half2_rn(p2, p3);
      pf[j][0] = *reinterpret_cast<uint32_t*>(&h01);
      pf[j][1] = *reinterpret_cast<uint32_t*>(&h23);
    }
#pragma unroll
    for (int off = 1; off <= 2; off <<= 1) {
      sum0 += __shfl_xor_sync(0xffffffffu, sum0, off);
      sum1 += __shfl_xor_sync(0xffffffffu, sum1, off);
    }
    l0 = l0 * corr0 + sum0;
    l1 = l1 * corr1 + sum1;
#pragma unroll
    for (int np = 0; np < 8; np++) {
      oacc[np][0] *= corr0; oacc[np][1] *= corr0;
      oacc[np][2] *= corr1; oacc[np][3] *= corr1;
    }

#pragma unroll
    for (int kk = 0; kk < 4; kk++) {
      uint32_t a[4] = { pf[2 * kk][0], pf[2 * kk][1],
                        pf[2 * kk + 1][0], pf[2 * kk + 1][1] };
#pragma unroll
      for (int np = 0; np < 4; np++) {
        uint32_t r[4];
        ldsm_x4_t(r, vd + (uint32_t)(kk * 16 + (lane & 15)) * ATT_LD
                        + np * 32 + (lane >> 4) * 16);
        mma_f16(oacc[2 * np], a, r[0], r[1]);
        mma_f16(oacc[2 * np + 1], a, r[2], r[3]);
      }
    }
    __syncthreads();
  }

  const float inv0 = 1.0f / l0, inv1 = 1.0f / l1;
#pragma unroll
  for (int np = 0; np < 8; np++) {
    int col = h * D_HEAD + np * 8 + 2 * t;
    __half2 lo = __floats2half2_rn(oacc[np][0] * inv0, oacc[np][1] * inv0);
    __half2 hi = __floats2half2_rn(oacc[np][2] * inv1, oacc[np][3] * inv1);
    *reinterpret_cast<__half2*>(&z[(size_t)(b * S_LEN + row0) * D_MODEL + col]) = lo;
    *reinterpret_cast<__half2*>(&z[(size_t)(b * S_LEN + row1) * D_MODEL + col]) = hi;
  }
}

// -------------------- driver --------------------
template<bool GELU, bool ACCUM, bool OUTH, bool SWAP>
static void launch_hgemm(const __half* A, const __half* B, const float* bias,
                         void* C, int M, int K, int NB, int Nstore) {
  cudaFuncSetAttribute(hgemm<GELU, ACCUM, OUTH, SWAP>,
                       cudaFuncAttributeMaxDynamicSharedMemorySize, GEMM_SMEM);
  dim3 grid = SWAP ? dim3(M / 128, NB / 128) : dim3(NB / 128, M / 128);
  hgemm<GELU, ACCUM, OUTH, SWAP><<<grid, 256, GEMM_SMEM>>>(A, B, bias, C, M, K, NB, Nstore);
}

extern "C" void kernel_launch(void* const* d_in, const int* in_sizes, int n_in,
                              void* d_out, int out_size) {
  const int*   tokens = (const int*)  d_in[0];
  const float* W_E    = (const float*)d_in[1];
  const float* W_pos  = (const float*)d_in[2];
  const float* ln1_w  = (const float*)d_in[3];
  const float* ln1_b  = (const float*)d_in[4];
  const float* W_Q    = (const float*)d_in[5];
  const float* b_Q    = (const float*)d_in[6];
  const float* W_K    = (const float*)d_in[7];
  const float* b_K    = (const float*)d_in[8];
  const float* W_V    = (const float*)d_in[9];
  const float* b_V    = (const float*)d_in[10];
  const float* W_O    = (const float*)d_in[11];
  const float* b_O    = (const float*)d_in[12];
  const float* ln2_w  = (const float*)d_in[13];
  const float* ln2_b  = (const float*)d_in[14];
  const float* W_in   = (const float*)d_in[15];
  const float* b_in   = (const float*)d_in[16];
  const float* W_out  = (const float*)d_in[17];
  const float* b_out  = (const float*)d_in[18];
  const float* lnf_w  = (const float*)d_in[19];
  const float* lnf_b  = (const float*)d_in[20];
  const float* W_U    = (const float*)d_in[21];
  const float* b_U    = (const float*)d_in[22];
  float* out = (float*)d_out;

  float *resid, *bqkv;
  __half *xh, *qkvh, *zh, *hh, *wqkv, *wo, *win, *wout, *wu;
  cudaGetSymbolAddress((void**)&resid, g_resid);
  cudaGetSymbolAddress((void**)&xh,    g_xh);
  cudaGetSymbolAddress((void**)&qkvh,  g_qkvh);
  cudaGetSymbolAddress((void**)&zh,    g_zh);
  cudaGetSymbolAddress((void**)&hh,    g_hh);
  cudaGetSymbolAddress((void**)&wqkv,  g_wqkv);
  cudaGetSymbolAddress((void**)&bqkv,  g_bqkv);
  cudaGetSymbolAddress((void**)&wo,    g_wo);
  cudaGetSymbolAddress((void**)&win,   g_win);
  cudaGetSymbolAddress((void**)&wout,  g_wout);
  cudaGetSymbolAddress((void**)&wu,    g_wu);

  conv_qkv8<<<(N_LAYERS * D_MODEL * QKV_N) / 2048, 256>>>(W_Q, W_K, W_V, wqkv);
  pack_bias_qkv<<<(N_LAYERS * QKV_N) / 256, 256>>>(b_Q, b_K, b_V, bqkv);
  conv_flat8<<<(N_LAYERS * D_MODEL * D_MODEL) / 2048, 256>>>(W_O, wo);
  conv_flat8<<<(N_LAYERS * D_MODEL * D_MLP) / 2048, 256>>>(W_in, win);
  conv_flat8<<<(N_LAYERS * D_MLP * D_MODEL) / 2048, 256>>>(W_out, wout);
  {
    dim3 gv((N_VOCAB_PAD + 2047) / 2048, D_MODEL);
    conv_vocab8<<<gv, 256>>>(W_U, wu);
  }

  embed_kernel<<<N_TOKENS, 128>>>(tokens, W_E, W_pos, resid);

  dim3 gA(S_LEN / 64, N_HEADS, 2);

  for (int l = 0; l < N_LAYERS; l++) {
    size_t w1 = (size_t)l * D_MODEL * D_MODEL;
    size_t w2 = (size_t)l * D_MODEL * D_MLP;
    const float* l1w = ln1_w + (size_t)l * D_MODEL;
    const float* l1b = ln1_b + (size_t)l * D_MODEL;
    const float* l2w = ln2_w + (size_t)l * D_MODEL;
    const float* l2b = ln2_b + (size_t)l * D_MODEL;

    ln_kernel<<<N_TOKENS, 128>>>(resid, l1w, l1b, xh);
    launch_hgemm<false, false, true, false>(xh, wqkv + (size_t)l * D_MODEL * QKV_N,
                                            bqkv + (size_t)l * QKV_N, qkvh,
                                            N_TOKENS, D_MODEL, QKV_N, QKV_N);
    attn_tc<<<gA, 128>>>(qkvh, zh);
    launch_hgemm<false, true, false, false>(zh, wo + w1, b_O + (size_t)l * D_MODEL, resid,
                                            N_TOKENS, D_MODEL, D_MODEL, D_MODEL);
    ln_kernel<<<N_TOKENS, 128>>>(resid, l2w, l2b, xh);
    launch_hgemm<true, false, true, false>(xh, win + w2, b_in + (size_t)l * D_MLP, hh,
                                           N_TOKENS, D_MODEL, D_MLP, D_MLP);
    launch_hgemm<false, true, false, false>(hh, wout + w2, b_out + (size_t)l * D_MODEL, resid,
                                            N_TOKENS, D_MLP, D_MODEL, D_MODEL);
  }

  ln_kernel<<<N_TOKENS, 128>>>(resid, lnf_w, lnf_b, xh);
  launch_hgemm<false, false, false, true>(xh, wu, b_U, out,
                                          N_TOKENS, D_MODEL, N_VOCAB_PAD, N_VOCAB);
}

// round 15
// speedup vs baseline: 1.0953x; 1.0053x over previous
#include <cuda_runtime.h>
#include <cuda_fp16.h>
#include <cstdint>
#include <math.h>

#define S_LEN    2048
#define D_MODEL  1024
#define N_HEADS  16
#define D_HEAD   64
#define D_MLP    4096
#define N_LAYERS 4
#define N_VOCAB  50257
#define N_VOCAB_PAD 50304   // 393*128 (minimum multiple of 128 >= N_VOCAB)
#define N_TOKENS 4096
#define QKV_N    3072

// -------------------- scratch --------------------
__device__ float  g_resid[N_TOKENS * D_MODEL];
__device__ __half g_xh   [N_TOKENS * D_MODEL];
__device__ __half g_qkvh [N_TOKENS * QKV_N];
__device__ __half g_zh   [N_TOKENS * D_MODEL];
__device__ __half g_hh   [N_TOKENS * D_MLP];
__device__ __half g_wqkv [N_LAYERS * D_MODEL * QKV_N];
__device__ float  g_bqkv [N_LAYERS * QKV_N];
__device__ __half g_wo   [N_LAYERS * D_MODEL * D_MODEL];
__device__ __half g_win  [N_LAYERS * D_MODEL * D_MLP];
__device__ __half g_wout [N_LAYERS * D_MLP * D_MODEL];
__device__ __half g_wu   [D_MODEL * N_VOCAB_PAD];

#define WO_ELEMS   (N_LAYERS * D_MODEL * D_MODEL)
#define WIN_ELEMS  (N_LAYERS * D_MODEL * D_MLP)
#define WOUT_ELEMS (N_LAYERS * D_MLP * D_MODEL)
#define FLAT3_ELEMS (WO_ELEMS + WIN_ELEMS + WOUT_ELEMS)

// -------------------- helpers --------------------
__device__ __forceinline__ float gelu_new(float x) {
  float u = 0.7978845608028654f * (x + 0.044715f * x * x * x);
  return 0.5f * x * (1.0f + tanhf(u));
}
__device__ __forceinline__ void ldsm_x4(uint32_t (&r)[4], uint32_t addr) {
  asm volatile("ldmatrix.sync.aligned.m8n8.x4.shared.b16 {%0,%1,%2,%3}, [%4];"
    : "=r"(r[0]), "=r"(r[1]), "=r"(r[2]), "=r"(r[3]) : "r"(addr));
}
__device__ __forceinline__ void ldsm_x4_t(uint32_t (&r)[4], uint32_t addr) {
  asm volatile("ldmatrix.sync.aligned.m8n8.x4.trans.shared.b16 {%0,%1,%2,%3}, [%4];"
    : "=r"(r[0]), "=r"(r[1]), "=r"(r[2]), "=r"(r[3]) : "r"(addr));
}
__device__ __forceinline__ void mma_f16(float (&c)[4], const uint32_t (&a)[4],
                                        const uint32_t b0, const uint32_t b1) {
  asm volatile("mma.sync.aligned.m16n8k16.row.col.f32.f16.f16.f32 "
    "{%0,%1,%2,%3}, {%4,%5,%6,%7}, {%8,%9}, {%0,%1,%2,%3};"
    : "+f"(c[0]), "+f"(c[1]), "+f"(c[2]), "+f"(c[3])
    : "r"(a[0]), "r"(a[1]), "r"(a[2]), "r"(a[3]), "r"(b0), "r"(b1));
}
__device__ __forceinline__ void cp_async16(uint32_t dst, const void* src) {
  asm volatile("cp.async.cg.shared.global [%0], [%1], 16;\n" :: "r"(dst), "l"(src));
}
__device__ __forceinline__ uint4 pack8(const float4 a, const float4 b) {
  __half2 h0 = __floats2half2_rn(a.x, a.y);
  __half2 h1 = __floats2half2_rn(a.z, a.w);
  __half2 h2 = __floats2half2_rn(b.x, b.y);
  __half2 h3 = __floats2half2_rn(b.z, b.w);
  uint4 r;
  r.x = *reinterpret_cast<uint32_t*>(&h0);
  r.y = *reinterpret_cast<uint32_t*>(&h1);
  r.z = *reinterpret_cast<uint32_t*>(&h2);
  r.w = *reinterpret_cast<uint32_t*>(&h3);
  return r;
}

// -------------------- weight conversion --------------------
// merged flat conversion of W_O | W_in | W_out (one launch)
__global__ __launch_bounds__(256) void conv_flat3(
    const float* __restrict__ wo_in, const float* __restrict__ win_in,
    const float* __restrict__ wout_in,
    __half* __restrict__ wo_out, __half* __restrict__ win_out,
    __half* __restrict__ wout_out) {
  size_t i8 = ((size_t)blockIdx.x * 256 + threadIdx.x) * 8;
  const float* src;
  __half* dst;
  size_t off;
  if (i8 < WO_ELEMS) {
    src = wo_in; dst = wo_out; off = i8;
  } else if (i8 < WO_ELEMS + WIN_ELEMS) {
    src = win_in; dst = win_out; off = i8 - WO_ELEMS;
  } else {
    src = wout_in; dst = wout_out; off = i8 - WO_ELEMS - WIN_ELEMS;
  }
  float4 a = *reinterpret_cast<const float4*>(src + off);
  float4 b = *reinterpret_cast<const float4*>(src + off + 4);
  *reinterpret_cast<uint4*>(dst + off) = pack8(a, b);
}
__global__ __launch_bounds__(256) void conv_qkv8(
    const float* __restrict__ WQ, const float* __restrict__ WK,
    const float* __restrict__ WV, __half* __restrict__ out) {
  size_t i8 = ((size_t)blockIdx.x * 256 + threadIdx.x) * 8;
  int n = (int)(i8 % QKV_N);
  size_t lk = i8 / QKV_N;
  int k = (int)(lk % D_MODEL);
  int l = (int)(lk / D_MODEL);
  int which = n >> 10, nn = n & 1023;
  int h = nn >> 6, dh = nn & 63;
  const float* W = (which == 0) ? WQ : ((which == 1) ? WK : WV);
  const float* src = W + (((size_t)l * N_HEADS + h) * D_MODEL + k) * D_HEAD + dh;
  float4 a = *reinterpret_cast<const float4*>(src);
  float4 b = *reinterpret_cast<const float4*>(src + 4);
  *reinterpret_cast<uint4*>(out + i8) = pack8(a, b);
}
__global__ __launch_bounds__(256) void conv_vocab8(
    const float* __restrict__ in, __half* __restrict__ out) {
  int k = blockIdx.y;
  int n = blockIdx.x * 2048 + threadIdx.x * 8;
  if (n >= N_VOCAB_PAD) return;
  const float* row = in + (size_t)k * N_VOCAB;
  float f[8];
#pragma unroll
  for (int u = 0; u < 8; u++) {
    int c = n + u;
    f[u] = (c < N_VOCAB) ? __ldg(row + c) : 0.f;
  }
  float4 a = make_float4(f[0], f[1], f[2], f[3]);
  float4 b = make_float4(f[4], f[5], f[6], f[7]);
  *reinterpret_cast<uint4*>(out + (size_t)k * N_VOCAB_PAD + n) = pack8(a, b);
}
__global__ __launch_bounds__(256) void pack_bias_qkv(
    const float* __restrict__ bq, const float* __restrict__ bk,
    const float* __restrict__ bv, float* __restrict__ out) {
  int i = blockIdx.x * 256 + threadIdx.x;
  int n = i % QKV_N, l = i / QKV_N;
  const float* s = (n < 1024) ? bq : ((n < 2048) ? bk : bv);
  out[i] = s[l * 1024 + (n & 1023)];
}

// -------------------- fused embed + layer-0 LN1 --------------------
// resid = WE[tok]+Wpos ; xh = LN(resid)*w+b   (one pass, no resid re-read)
__global__ __launch_bounds__(128) void embed_ln_kernel(
    const int* __restrict__ tok, const float* __restrict__ WE,
    const float* __restrict__ Wp, const float* __restrict__ w,
    const float* __restrict__ b, float* __restrict__ resid,
    __half* __restrict__ out) {
  int row = blockIdx.x;
  int s = row & (S_LEN - 1);
  int t = threadIdx.x;
  int token = tok[row];
  const float4* we = reinterpret_cast<const float4*>(WE + (size_t)token * D_MODEL);
  const float4* wpp = reinterpret_cast<const float4*>(Wp + (size_t)s * D_MODEL);
  float4 e0 = we[t], e1 = we[t + 128];
  float4 p0 = wpp[t], p1 = wpp[t + 128];
  float4 v0, v1;
  v0.x = e0.x + p0.x; v0.y = e0.y + p0.y; v0.z = e0.z + p0.z; v0.w = e0.w + p0.w;
  v1.x = e1.x + p1.x; v1.y = e1.y + p1.y; v1.z = e1.z + p1.z; v1.w = e1.w + p1.w;
  float4* r = reinterpret_cast<float4*>(resid + (size_t)row * D_MODEL);
  r[t] = v0;
  r[t + 128] = v1;
  float sm  = v0.x + v0.y + v0.z + v0.w + v1.x + v1.y + v1.z + v1.w;
  float ss = v0.x*v0.x + v0.y*v0.y + v0.z*v0.z + v0.w*v0.w
           + v1.x*v1.x + v1.y*v1.y + v1.z*v1.z + v1.w*v1.w;
#pragma unroll
  for (int off = 16; off; off >>= 1) {
    sm += __shfl_xor_sync(0xffffffffu, sm, off);
    ss += __shfl_xor_sync(0xffffffffu, ss, off);
  }
  __shared__ float shs[4], shss[4];
  int wid = t >> 5;
  if ((t & 31) == 0) { shs[wid] = sm; shss[wid] = ss; }
  __syncthreads();
  float tot  = shs[0] + shs[1] + shs[2] + shs[3];
  float tots = shss[0] + shss[1] + shss[2] + shss[3];
  float mean = tot * (1.0f / D_MODEL);
  float var  = tots * (1.0f / D_MODEL) - mean * mean;
  float rstd = rsqrtf(var + 1e-5f);
  const float4* wp = reinterpret_cast<const float4*>(w);
  const float4* bp = reinterpret_cast<const float4*>(b);
  float4 w0 = wp[t], w1 = wp[t + 128];
  float4 b0 = bp[t], b1 = bp[t + 128];
  __half2* o2 = reinterpret_cast<__half2*>(out + (size_t)row * D_MODEL);
  o2[2 * t]     = __floats2half2_rn((v0.x - mean) * rstd * w0.x + b0.x,
                                    (v0.y - mean) * rstd * w0.y + b0.y);
  o2[2 * t + 1] = __floats2half2_rn((v0.z - mean) * rstd * w0.z + b0.z,
                                    (v0.w - mean) * rstd * w0.w + b0.w);
  o2[2 * (t + 128)]     = __floats2half2_rn((v1.x - mean) * rstd * w1.x + b1.x,
                                            (v1.y - mean) * rstd * w1.y + b1.y);
  o2[2 * (t + 128) + 1] = __floats2half2_rn((v1.z - mean) * rstd * w1.z + b1.z,
                                            (v1.w - mean) * rstd * w1.w + b1.w);
}

// -------------------- layernorm (128 thr, 2 indep float4/thread) ---------
__global__ __launch_bounds__(128) void ln_kernel(
    const float* __restrict__ in, const float* __restrict__ w,
    const float* __restrict__ b, __half* __restrict__ out) {
  int row = blockIdx.x;
  int t = threadIdx.x;
  const float4* ip = reinterpret_cast<const float4*>(in + (size_t)row * D_MODEL);
  float4 v0 = ip[t], v1 = ip[t + 128];
  float s  = v0.x + v0.y + v0.z + v0.w + v1.x + v1.y + v1.z + v1.w;
  float ss = v0.x*v0.x + v0.y*v0.y + v0.z*v0.z + v0.w*v0.w
           + v1.x*v1.x + v1.y*v1.y + v1.z*v1.z + v1.w*v1.w;
#pragma unroll
  for (int off = 16; off; off >>= 1) {
    s  += __shfl_xor_sync(0xffffffffu, s,  off);
    ss += __shfl_xor_sync(0xffffffffu, ss, off);
  }
  __shared__ float shs[4], shss[4];
  int wid = t >> 5;
  if ((t & 31) == 0) { shs[wid] = s; shss[wid] = ss; }
  __syncthreads();
  float tot  = shs[0] + shs[1] + shs[2] + shs[3];
  float tots = shss[0] + shss[1] + shss[2] + shss[3];
  float mean = tot * (1.0f / D_MODEL);
  float var  = tots * (1.0f / D_MODEL) - mean * mean;
  float rstd = rsqrtf(var + 1e-5f);
  const float4* wp = reinterpret_cast<const float4*>(w);
  const float4* bp = reinterpret_cast<const float4*>(b);
  float4 w0 = wp[t], w1 = wp[t + 128];
  float4 b0 = bp[t], b1 = bp[t + 128];
  __half2* o2 = reinterpret_cast<__half2*>(out + (size_t)row * D_MODEL);
  o2[2 * t]     = __floats2half2_rn((v0.x - mean) * rstd * w0.x + b0.x,
                                    (v0.y - mean) * rstd * w0.y + b0.y);
  o2[2 * t + 1] = __floats2half2_rn((v0.z - mean) * rstd * w0.z + b0.z,
                                    (v0.w - mean) * rstd * w0.w + b0.w);
  o2[2 * (t + 128)]     = __floats2half2_rn((v1.x - mean) * rstd * w1.x + b1.x,
                                            (v1.y - mean) * rstd * w1.y + b1.y);
  o2[2 * (t + 128) + 1] = __floats2half2_rn((v1.z - mean) * rstd * w1.z + b1.z,
                                            (v1.w - mean) * rstd * w1.w + b1.w);
}

// -------------------- FP16 tensor-core GEMM (128x128, warp 64x32) --------
#define KT        64
#define LDA_B     144
#define LDB_B     272
#define A_BYTES   (128 * LDA_B)
#define B_BYTES   (KT * LDB_B)
#define STAGE_B   (A_BYTES + B_BYTES)
#define NSTAGES   3
#define GEMM_SMEM (NSTAGES * STAGE_B)

template<bool GELU, bool ACCUM, bool OUTH, bool SWAP>
__global__ __launch_bounds__(256) void hgemm(
    const __half* __restrict__ A, const __half* __restrict__ B,
    const float* __restrict__ bias, void* __restrict__ Cv,
    int M, int K, int NB, int Nstore) {
  extern __shared__ __align__(16) char smem[];
  const uint32_t sm = (uint32_t)__cvta_generic_to_shared(smem);

  const int tid  = threadIdx.x;
  const int lane = tid & 31, warp = tid >> 5;
  const int wm = (warp >> 2) * 64;
  const int wn = (warp & 3) * 32;
  const int g = lane >> 2, t = lane & 3;
  const int brow = (SWAP ? blockIdx.x : blockIdx.y) * 128;
  const int bcol = (SWAP ? blockIdx.y : blockIdx.x) * 128;
  const uint32_t laneRow = lane & 15, laneHi = lane >> 4;

  float acc[16][4];
#pragma unroll
  for (int i = 0; i < 16; i++)
#pragma unroll
    for (int j = 0; j < 4; j++) acc[i][j] = 0.f;

  const int NT = K / KT;

  auto stage = [&](int tt) {
    const int k0 = tt * KT;
    const uint32_t sA = sm + (uint32_t)(tt % NSTAGES) * STAGE_B;
    const uint32_t sB = sA + A_BYTES;
    {
      int slot = tid;
#pragma unroll
      for (int i = 0; i < 4; i++) {
        int r = slot >> 3, ch = slot & 7;
        cp_async16(sA + (uint32_t)r * LDA_B + ch * 16,
                   A + (size_t)(brow + r) * K + k0 + ch * 8);
        slot += 256;
      }
    }
    {
      int slot = tid;
#pragma unroll
      for (int i = 0; i < 4; i++) {
        int r = slot >> 4, ch = slot & 15;
        cp_async16(sB + (uint32_t)r * LDB_B + ch * 16,
                   B + (size_t)(k0 + r) * NB + bcol + ch * 8);
        slot += 256;
      }
    }
    asm volatile("cp.async.commit_group;\n" ::: "memory");
  };

  stage(0);
  if (NT > 1) stage(1);

  for (int tt = 0; tt < NT; tt++) {
    if (tt + 1 < NT) {
      asm volatile("cp.async.wait_group 1;\n" ::: "memory");
    } else {
      asm volatile("cp.async.wait_group 0;\n" ::: "memory");
    }
    __syncthreads();
    if (tt + 2 < NT) stage(tt + 2);

    const uint32_t sA = sm + (uint32_t)(tt % NSTAGES) * STAGE_B;
    const uint32_t sB = sA + A_BYTES;

#pragma unroll
    for (int ik = 0; ik < 4; ik++) {
      uint32_t a[4][4];
#pragma unroll
      for (int im = 0; im < 4; im++)
        ldsm_x4(a[im], sA + (uint32_t)(wm + im * 16 + laneRow) * LDA_B
                          + ik * 32 + laneHi * 16);
      uint32_t b[4][2];
#pragma unroll
      for (int jp = 0; jp < 2; jp++) {
        uint32_t r[4];
        ldsm_x4_t(r, sB + (uint32_t)(ik * 16 + laneRow) * LDB_B
                        + (uint32_t)(wn + jp * 16 + laneHi * 8) * 2);
        b[2 * jp][0] = r[0]; b[2 * jp][1] = r[1];
        b[2 * jp + 1][0] = r[2]; b[2 * jp + 1][1] = r[3];
      }
#pragma unroll
      for (int im = 0; im < 4; im++)
#pragma unroll
        for (int jn = 0; jn < 4; jn++)
          mma_f16(acc[im * 4 + jn], a[im], b[jn][0], b[jn][1]);
    }
    __syncthreads();
  }

  float*  Cf = (float*)Cv;
  __half* Ch = (__half*)Cv;
#pragma unroll
  for (int im = 0; im < 4; im++) {
#pragma unroll
    for (int jn = 0; jn < 4; jn++) {
      const float* c = acc[im * 4 + jn];
      int r0 = brow + wm + im * 16 + g;
      int c0 = bcol + wn + jn * 8 + 2 * t;
#pragma unroll
      for (int u = 0; u < 4; u++) {
        int r = r0 + (u >> 1) * 8;
        int cc = c0 + (u & 1);
        if (cc < Nstore) {
          float val = c[u] + bias[cc];
          if (GELU) val = gelu_new(val);
          size_t idx = (size_t)r * Nstore + cc;
          if (OUTH) {
            Ch[idx] = __float2half(val);
          } else {
            if (ACCUM) val += Cf[idx];
            Cf[idx] = val;
          }
        }
      }
    }
  }
}

// -------------------- tensor-core flash attention --------------------
#define ATT_LD 144
__global__ __launch_bounds__(128) void attn_tc(
    const __half* __restrict__ qkv, __half* __restrict__ z) {
  const int b = blockIdx.z, h = blockIdx.y;
  const int q0 = (gridDim.x - 1 - blockIdx.x) * 64;
  const int tid = threadIdx.x;
  const int warp = tid >> 5, lane = tid & 31;
  const int g = lane >> 2, t = lane & 3;

  __shared__ __align__(16) __half sQ[64 * 72];
  __shared__ __align__(16) __half sK[2][64 * 72];
  __shared__ __align__(16) __half sV[2][64 * 72];
  const uint32_t qb = (uint32_t)__cvta_generic_to_shared(sQ);
  const uint32_t kb0 = (uint32_t)__cvta_generic_to_shared(sK[0]);
  const uint32_t kb1 = (uint32_t)__cvta_generic_to_shared(sK[1]);
  const uint32_t vb0 = (uint32_t)__cvta_generic_to_shared(sV[0]);
  const uint32_t vb1 = (uint32_t)__cvta_generic_to_shared(sV[1]);

  for (int slot = tid; slot < 512; slot += 128) {
    int r = slot >> 3, c = slot & 7;
    *reinterpret_cast<uint4*>(&sQ[r * 72 + c * 8]) =
      *reinterpret_cast<const uint4*>(
        qkv + (size_t)(b * S_LEN + q0 + r) * QKV_N + h * D_HEAD + c * 8);
  }
  __syncthreads();

  uint32_t qf[4][4];
#pragma unroll
  for (int ik = 0; ik < 4; ik++)
    ldsm_x4(qf[ik], qb + (uint32_t)(warp * 16 + (lane & 15)) * ATT_LD
                       + ik * 32 + (lane >> 4) * 16);

  const int row0 = q0 + warp * 16 + g;
  const int row1 = row0 + 8;

  float m0 = -INFINITY, m1 = -INFINITY, l0 = 0.f, l1 = 0.f;
  float oacc[8][4];
#pragma unroll
  for (int i = 0; i < 8; i++)
#pragma unroll
    for (int j = 0; j < 4; j++) oacc[i][j] = 0.f;

  const int ntiles = (q0 >> 6) + 1;

  auto stageKV = [&](int tile) {
    const int kt = tile * 64;
    const uint32_t kd = (tile & 1) ? kb1 : kb0;
    const uint32_t vd = (tile & 1) ? vb1 : vb0;
    for (int slot = tid; slot < 512; slot += 128) {
      int r = slot >> 3, c = slot & 7;
      const __half* src = qkv + (size_t)(b * S_LEN + kt + r) * QKV_N
                              + 1024 + h * D_HEAD + c * 8;
      cp_async16(kd + (uint32_t)r * ATT_LD + c * 16, src);
      cp_async16(vd + (uint32_t)r * ATT_LD + c * 16, src + 1024);
    }
    asm volatile("cp.async.commit_group;\n" ::: "memory");
  };

  stageKV(0);

  for (int tile = 0; tile < ntiles; tile++) {
    asm volatile("cp.async.wait_group 0;\n" ::: "memory");
    __syncthreads();
    if (tile + 1 < ntiles) stageKV(tile + 1);

    const uint32_t kd = (tile & 1) ? kb1 : kb0;
    const uint32_t vd = (tile & 1) ? vb1 : vb0;
    const int kt = tile * 64;

    float sacc[8][4];
#pragma unroll
    for (int j = 0; j < 8; j++) {
#pragma unroll
      for (int u = 0; u < 4; u++) sacc[j][u] = 0.f;
      uint32_t bk0[4], bk1[4];
      uint32_t base = kd + (uint32_t)(j * 8 + (lane & 7)) * ATT_LD + (lane >> 3) * 16;
      ldsm_x4(bk0, base);
      ldsm_x4(bk1, base + 64);
      mma_f16(sacc[j], qf[0], bk0[0], bk0[1]);
      mma_f16(sacc[j], qf[1], bk0[2], bk0[3]);
      mma_f16(sacc[j], qf[2], bk1[0], bk1[1]);
      mma_f16(sacc[j], qf[3], bk1[2], bk1[3]);
    }

    float tmx0 = -1e30f, tmx1 = -1e30f;
#pragma unroll
    for (int j = 0; j < 8; j++) {
      int kbase = kt + j * 8 + 2 * t;
      sacc[j][0] = (kbase     <= row0) ? sacc[j][0] * 0.125f : -1e30f;
      sacc[j][1] = (kbase + 1 <= row0) ? sacc[j][1] * 0.125f : -1e30f;
      sacc[j][2] = (kbase     <= row1) ? sacc[j][2] * 0.125f : -1e30f;
      sacc[j][3] = (kbase + 1 <= row1) ? sacc[j][3] * 0.125f : -1e30f;
      tmx0 = fmaxf(tmx0, fmaxf(sacc[j][0], sacc[j][1]));
      tmx1 = fmaxf(tmx1, fmaxf(sacc[j][2], sacc[j][3]));
    }
#pragma unroll
    for (int off = 1; off <= 2; off <<= 1) {
      tmx0 = fmaxf(tmx0, __shfl_xor_sync(0xffffffffu, tmx0, off));
      tmx1 = fmaxf(tmx1, __shfl_xor_sync(0xffffffffu, tmx1, off));
    }
    float mn0 = fmaxf(m0, tmx0), mn1 = fmaxf(m1, tmx1);
    float corr0 = __expf(m0 - mn0), corr1 = __expf(m1 - mn1);
    m0 = mn0; m1 = mn1;

    uint32_t pf[8][2];
    float sum0 = 0.f, sum1 = 0.f;
#pragma unroll
    for (int j = 0; j < 8; j++) {
      float p0 = __expf(sacc[j][0] - mn0);
      float p1 = __expf(sacc[j][1] - mn0);
      float p2 = __expf(sacc[j][2] - mn1);
      float p3 = __expf(sacc[j][3] - mn1);
      sum0 += p0 + p1; sum1 += p2 + p3;
      __half2 h01 = __floats2half2_rn(p0, p1);
      __half2 h23 = __floats2half2_rn(p2, p3);
      pf[j][0] = *reinterpret_cast<uint32_t*>(&h01);
      pf[j][1] = *reinterpret_cast<uint32_t*>(&h23);
    }
#pragma unroll
    for (int off = 1; off <= 2; off <<= 1) {
      sum0 += __shfl_xor_sync(0xffffffffu, sum0, off);
      sum1 += __shfl_xor_sync(0xffffffffu, sum1, off);
    }
    l0 = l0 * corr0 + sum0;
    l1 = l1 * corr1 + sum1;
#pragma unroll
    for (int np = 0; np < 8; np++) {
      oacc[np][0] *= corr0; oacc[np][1] *= corr0;
      oacc[np][2] *= corr1; oacc[np][3] *= corr1;
    }

#pragma unroll
    for (int kk = 0; kk < 4; kk++) {
      uint32_t a[4] = { pf[2 * kk][0], pf[2 * kk][1],
                        pf[2 * kk + 1][0], pf[2 * kk + 1][1] };
#pragma unroll
      for (int np = 0; np < 4; np++) {
        uint32_t r[4];
        ldsm_x4_t(r, vd + (uint32_t)(kk * 16 + (lane & 15)) * ATT_LD
                        + np * 32 + (lane >> 4) * 16);
        mma_f16(oacc[2 * np], a, r[0], r[1]);
        mma_f16(oacc[2 * np + 1], a, r[2], r[3]);
      }
    }
    __syncthreads();
  }

  const float inv0 = 1.0f / l0, inv1 = 1.0f / l1;
#pragma unroll
  for (int np = 0; np < 8; np++) {
    int col = h * D_HEAD + np * 8 + 2 * t;
    __half2 lo = __floats2half2_rn(oacc[np][0] * inv0, oacc[np][1] * inv0);
    __half2 hi = __floats2half2_rn(oacc[np][2] * inv1, oacc[np][3] * inv1);
    *reinterpret_cast<__half2*>(&z[(size_t)(b * S_LEN + row0) * D_MODEL + col]) = lo;
    *reinterpret_cast<__half2*>(&z[(size_t)(b * S_LEN + row1) * D_MODEL + col]) = hi;
  }
}

// -------------------- driver --------------------
template<bool GELU, bool ACCUM, bool OUTH, bool SWAP>
static void launch_hgemm(const __half* A, const __half* B, const float* bias,
                         void* C, int M, int K, int NB, int Nstore) {
  cudaFuncSetAttribute(hgemm<GELU, ACCUM, OUTH, SWAP>,
                       cudaFuncAttributeMaxDynamicSharedMemorySize, GEMM_SMEM);
  dim3 grid = SWAP ? dim3(M / 128, NB / 128) : dim3(NB / 128, M / 128);
  hgemm<GELU, ACCUM, OUTH, SWAP><<<grid, 256, GEMM_SMEM>>>(A, B, bias, C, M, K, NB, Nstore);
}

extern "C" void kernel_launch(void* const* d_in, const int* in_sizes, int n_in,
                              void* d_out, int out_size) {
  const int*   tokens = (const int*)  d_in[0];
  const float* W_E    = (const float*)d_in[1];
  const float* W_pos  = (const float*)d_in[2];
  const float* ln1_w  = (const float*)d_in[3];
  const float* ln1_b  = (const float*)d_in[4];
  const float* W_Q    = (const float*)d_in[5];
  const float* b_Q    = (const float*)d_in[6];
  const float* W_K    = (const float*)d_in[7];
  const float* b_K    = (const float*)d_in[8];
  const float* W_V    = (const float*)d_in[9];
  const float* b_V    = (const float*)d_in[10];
  const float* W_O    = (const float*)d_in[11];
  const float* b_O    = (const float*)d_in[12];
  const float* ln2_w  = (const float*)d_in[13];
  const float* ln2_b  = (const float*)d_in[14];
  const float* W_in   = (const float*)d_in[15];
  const float* b_in   = (const float*)d_in[16];
  const float* W_out  = (const float*)d_in[17];
  const float* b_out  = (const float*)d_in[18];
  const float* lnf_w  = (const float*)d_in[19];
  const float* lnf_b  = (const float*)d_in[20];
  const float* W_U    = (const float*)d_in[21];
  const float* b_U    = (const float*)d_in[22];
  float* out = (float*)d_out;

  float *resid, *bqkv;
  __half *xh, *qkvh, *zh, *hh, *wqkv, *wo, *win, *wout, *wu;
  cudaGetSymbolAddress((void**)&resid, g_resid);
  cudaGetSymbolAddress((void**)&xh,    g_xh);
  cudaGetSymbolAddress((void**)&qkvh,  g_qkvh);
  cudaGetSymbolAddress((void**)&zh,    g_zh);
  cudaGetSymbolAddress((void**)&hh,    g_hh);
  cudaGetSymbolAddress((void**)&wqkv,  g_wqkv);
  cudaGetSymbolAddress((void**)&bqkv,  g_bqkv);
  cudaGetSymbolAddress((void**)&wo,    g_wo);
  cudaGetSymbolAddress((void**)&win,   g_win);
  cudaGetSymbolAddress((void**)&wout,  g_wout);
  cudaGetSymbolAddress((void**)&wu,    g_wu);

  conv_qkv8<<<(N_LAYERS * D_MODEL * QKV_N) / 2048, 256>>>(W_Q, W_K, W_V, wqkv);
  pack_bias_qkv<<<(N_LAYERS * QKV_N) / 256, 256>>>(b_Q, b_K, b_V, bqkv);
  conv_flat3<<<FLAT3_ELEMS / 2048, 256>>>(W_O, W_in, W_out, wo, win, wout);
  {
    dim3 gv((N_VOCAB_PAD + 2047) / 2048, D_MODEL);
    conv_vocab8<<<gv, 256>>>(W_U, wu);
  }

  dim3 gA(S_LEN / 64, N_HEADS, 2);

  for (int l = 0; l < N_LAYERS; l++) {
    size_t w1 = (size_t)l * D_MODEL * D_MODEL;
    size_t w2 = (size_t)l * D_MODEL * D_MLP;
    const float* l1w = ln1_w + (size_t)l * D_MODEL;
    const float* l1b = ln1_b + (size_t)l * D_MODEL;
    const float* l2w = ln2_w + (size_t)l * D_MODEL;
    const float* l2b = ln2_b + (size_t)l * D_MODEL;

    if (l == 0) {
      // fused: resid = WE[tok]+Wpos ; xh = LN1(resid)
      embed_ln_kernel<<<N_TOKENS, 128>>>(tokens, W_E, W_pos, l1w, l1b, resid, xh);
    } else {
      ln_kernel<<<N_TOKENS, 128>>>(resid, l1w, l1b, xh);
    }
    launch_hgemm<false, false, true, false>(xh, wqkv + (size_t)l * D_MODEL * QKV_N,
                                            bqkv + (size_t)l * QKV_N, qkvh,
                                            N_TOKENS, D_MODEL, QKV_N, QKV_N);
    attn_tc<<<gA, 128>>>(qkvh, zh);
    launch_hgemm<false, true, false, false>(zh, wo + w1, b_O + (size_t)l * D_MODEL, resid,
                                            N_TOKENS, D_MODEL, D_MODEL, D_MODEL);
    ln_kernel<<<N_TOKENS, 128>>>(resid, l2w, l2b, xh);
    launch_hgemm<true, false, true, false>(xh, win + w2, b_in + (size_t)l * D_MLP, hh,
                                           N_TOKENS, D_MODEL, D_MLP, D_MLP);
    launch_hgemm<false, true, false, false>(hh, wout + w2, b_out + (size_t)l * D_MODEL, resid,
                                            N_TOKENS, D_MLP, D_MODEL, D_MODEL);
  }

  ln_kernel<<<N_TOKENS, 128>>>(resid, lnf_w, lnf_b, xh);
  launch_hgemm<false, false, false, true>(xh, wu, b_U, out,
                                          N_TOKENS, D_MODEL, N_VOCAB_PAD, N_VOCAB);
}

// round 16
// speedup vs baseline: 1.0975x; 1.0020x over previous
#include <cuda_runtime.h>
#include <cuda_fp16.h>
#include <cstdint>
#include <math.h>

#define S_LEN    2048
#define D_MODEL  1024
#define N_HEADS  16
#define D_HEAD   64
#define D_MLP    4096
#define N_LAYERS 4
#define N_VOCAB  50257
#define N_VOCAB_PAD 50304   // 393*128
#define N_TOKENS 4096
#define QKV_N    3072

// -------------------- scratch --------------------
__device__ float  g_resid[N_TOKENS * D_MODEL];
__device__ __half g_xh   [N_TOKENS * D_MODEL];
__device__ __half g_qkvh [N_TOKENS * QKV_N];
__device__ __half g_zh   [N_TOKENS * D_MODEL];
__device__ __half g_hh   [N_TOKENS * D_MLP];
__device__ __half g_wqkv [N_LAYERS * D_MODEL * QKV_N];
__device__ float  g_bqkv [N_LAYERS * QKV_N];
__device__ __half g_wo   [N_LAYERS * D_MODEL * D_MODEL];
__device__ __half g_win  [N_LAYERS * D_MODEL * D_MLP];
__device__ __half g_wout [N_LAYERS * D_MLP * D_MODEL];
__device__ __half g_wu   [D_MODEL * N_VOCAB_PAD];

#define WO_ELEMS    (N_LAYERS * D_MODEL * D_MODEL)
#define WIN_ELEMS   (N_LAYERS * D_MODEL * D_MLP)
#define WOUT_ELEMS  (N_LAYERS * D_MLP * D_MODEL)
// 8-element units per section
#define VOCAB_UNITS (D_MODEL * N_VOCAB_PAD / 8)                  // 6,438,912
#define QKV_UNITS   (N_LAYERS * D_MODEL * QKV_N / 8)             // 1,572,864
#define WO_UNITS    (WO_ELEMS / 8)
#define WIN_UNITS   (WIN_ELEMS / 8)
#define WOUT_UNITS  (WOUT_ELEMS / 8)
#define FLAT3_UNITS (WO_UNITS + WIN_UNITS + WOUT_UNITS)          // 4,718,592
#define TOTAL_UNITS (VOCAB_UNITS + QKV_UNITS + FLAT3_UNITS)      // 12,730,368

// -------------------- helpers --------------------
__device__ __forceinline__ float gelu_new(float x) {
  float u = 0.7978845608028654f * (x + 0.044715f * x * x * x);
  return 0.5f * x * (1.0f + tanhf(u));
}
__device__ __forceinline__ void ldsm_x4(uint32_t (&r)[4], uint32_t addr) {
  asm volatile("ldmatrix.sync.aligned.m8n8.x4.shared.b16 {%0,%1,%2,%3}, [%4];"
    : "=r"(r[0]), "=r"(r[1]), "=r"(r[2]), "=r"(r[3]) : "r"(addr));
}
__device__ __forceinline__ void ldsm_x4_t(uint32_t (&r)[4], uint32_t addr) {
  asm volatile("ldmatrix.sync.aligned.m8n8.x4.trans.shared.b16 {%0,%1,%2,%3}, [%4];"
    : "=r"(r[0]), "=r"(r[1]), "=r"(r[2]), "=r"(r[3]) : "r"(addr));
}
__device__ __forceinline__ void mma_f16(float (&c)[4], const uint32_t (&a)[4],
                                        const uint32_t b0, const uint32_t b1) {
  asm volatile("mma.sync.aligned.m16n8k16.row.col.f32.f16.f16.f32 "
    "{%0,%1,%2,%3}, {%4,%5,%6,%7}, {%8,%9}, {%0,%1,%2,%3};"
    : "+f"(c[0]), "+f"(c[1]), "+f"(c[2]), "+f"(c[3])
    : "r"(a[0]), "r"(a[1]), "r"(a[2]), "r"(a[3]), "r"(b0), "r"(b1));
}
__device__ __forceinline__ void cp_async16(uint32_t dst, const void* src) {
  asm volatile("cp.async.cg.shared.global [%0], [%1], 16;\n" :: "r"(dst), "l"(src));
}
__device__ __forceinline__ uint4 pack8(const float4 a, const float4 b) {
  __half2 h0 = __floats2half2_rn(a.x, a.y);
  __half2 h1 = __floats2half2_rn(a.z, a.w);
  __half2 h2 = __floats2half2_rn(b.x, b.y);
  __half2 h3 = __floats2half2_rn(b.z, b.w);
  uint4 r;
  r.x = *reinterpret_cast<uint32_t*>(&h0);
  r.y = *reinterpret_cast<uint32_t*>(&h1);
  r.z = *reinterpret_cast<uint32_t*>(&h2);
  r.w = *reinterpret_cast<uint32_t*>(&h3);
  return r;
}

// -------------------- merged weight conversion (one kernel) --------------
// unit u covers 8 consecutive output halves. Sections (in order):
//   [0, VOCAB)          : W_U -> g_wu   (scalar loads, zero-pad, per-row)
//   [VOCAB, +QKV)       : W_Q|W_K|W_V interleave -> g_wqkv (float4 loads)
//   [.., +FLAT3)        : W_O | W_in | W_out flat copies (float4 loads)
__global__ __launch_bounds__(256) void conv_all(
    const float* __restrict__ WU,
    const float* __restrict__ WQ, const float* __restrict__ WK,
    const float* __restrict__ WV,
    const float* __restrict__ WO, const float* __restrict__ WIN,
    const float* __restrict__ WOUT,
    __half* __restrict__ wu, __half* __restrict__ wqkv,
    __half* __restrict__ wo, __half* __restrict__ win,
    __half* __restrict__ wout) {
  size_t u = (size_t)blockIdx.x * 256 + threadIdx.x;
  if (u < VOCAB_UNITS) {
    int k = (int)(u / (N_VOCAB_PAD / 8));
    int n = (int)(u % (N_VOCAB_PAD / 8)) * 8;
    const float* row = WU + (size_t)k * N_VOCAB;
    float f[8];
#pragma unroll
    for (int i = 0; i < 8; i++) {
      int c = n + i;
      f[i] = (c < N_VOCAB) ? __ldg(row + c) : 0.f;
    }
    float4 a = make_float4(f[0], f[1], f[2], f[3]);
    float4 b = make_float4(f[4], f[5], f[6], f[7]);
    *reinterpret_cast<uint4*>(wu + (size_t)k * N_VOCAB_PAD + n) = pack8(a, b);
    return;
  }
  u -= VOCAB_UNITS;
  if (u < QKV_UNITS) {
    size_t i8 = u * 8;
    int n = (int)(i8 % QKV_N);
    size_t lk = i8 / QKV_N;
    int k = (int)(lk % D_MODEL);
    int l = (int)(lk / D_MODEL);
    int which = n >> 10, nn = n & 1023;
    int h = nn >> 6, dh = nn & 63;
    const float* W = (which == 0) ? WQ : ((which == 1) ? WK : WV);
    const float* src = W + (((size_t)l * N_HEADS + h) * D_MODEL + k) * D_HEAD + dh;
    float4 a = *reinterpret_cast<const float4*>(src);
    float4 b = *reinterpret_cast<const float4*>(src + 4);
    *reinterpret_cast<uint4*>(wqkv + i8) = pack8(a, b);
    return;
  }
  u -= QKV_UNITS;
  const float* src;
  __half* dst;
  size_t off;
  if (u < WO_UNITS) {
    src = WO; dst = wo; off = u * 8;
  } else if (u < WO_UNITS + WIN_UNITS) {
    src = WIN; dst = win; off = (u - WO_UNITS) * 8;
  } else {
    src = WOUT; dst = wout; off = (u - WO_UNITS - WIN_UNITS) * 8;
  }
  float4 a = *reinterpret_cast<const float4*>(src + off);
  float4 b = *reinterpret_cast<const float4*>(src + off + 4);
  *reinterpret_cast<uint4*>(dst + off) = pack8(a, b);
}

__global__ __launch_bounds__(256) void pack_bias_qkv(
    const float* __restrict__ bq, const float* __restrict__ bk,
    const float* __restrict__ bv, float* __restrict__ out) {
  int i = blockIdx.x * 256 + threadIdx.x;
  int n = i % QKV_N, l = i / QKV_N;
  const float* s = (n < 1024) ? bq : ((n < 2048) ? bk : bv);
  out[i] = s[l * 1024 + (n & 1023)];
}

// -------------------- fused embed + layer-0 LN1 --------------------
__global__ __launch_bounds__(128) void embed_ln_kernel(
    const int* __restrict__ tok, const float* __restrict__ WE,
    const float* __restrict__ Wp, const float* __restrict__ w,
    const float* __restrict__ b, float* __restrict__ resid,
    __half* __restrict__ out) {
  int row = blockIdx.x;
  int s = row & (S_LEN - 1);
  int t = threadIdx.x;
  int token = tok[row];
  const float4* we = reinterpret_cast<const float4*>(WE + (size_t)token * D_MODEL);
  const float4* wpp = reinterpret_cast<const float4*>(Wp + (size_t)s * D_MODEL);
  float4 e0 = we[t], e1 = we[t + 128];
  float4 p0 = wpp[t], p1 = wpp[t + 128];
  float4 v0, v1;
  v0.x = e0.x + p0.x; v0.y = e0.y + p0.y; v0.z = e0.z + p0.z; v0.w = e0.w + p0.w;
  v1.x = e1.x + p1.x; v1.y = e1.y + p1.y; v1.z = e1.z + p1.z; v1.w = e1.w + p1.w;
  float4* r = reinterpret_cast<float4*>(resid + (size_t)row * D_MODEL);
  r[t] = v0;
  r[t + 128] = v1;
  float sm  = v0.x + v0.y + v0.z + v0.w + v1.x + v1.y + v1.z + v1.w;
  float ss = v0.x*v0.x + v0.y*v0.y + v0.z*v0.z + v0.w*v0.w
           + v1.x*v1.x + v1.y*v1.y + v1.z*v1.z + v1.w*v1.w;
#pragma unroll
  for (int off = 16; off; off >>= 1) {
    sm += __shfl_xor_sync(0xffffffffu, sm, off);
    ss += __shfl_xor_sync(0xffffffffu, ss, off);
  }
  __shared__ float shs[4], shss[4];
  int wid = t >> 5;
  if ((t & 31) == 0) { shs[wid] = sm; shss[wid] = ss; }
  __syncthreads();
  float tot  = shs[0] + shs[1] + shs[2] + shs[3];
  float tots = shss[0] + shss[1] + shss[2] + shss[3];
  float mean = tot * (1.0f / D_MODEL);
  float var  = tots * (1.0f / D_MODEL) - mean * mean;
  float rstd = rsqrtf(var + 1e-5f);
  const float4* wp = reinterpret_cast<const float4*>(w);
  const float4* bp = reinterpret_cast<const float4*>(b);
  float4 w0 = wp[t], w1 = wp[t + 128];
  float4 b0 = bp[t], b1 = bp[t + 128];
  __half2* o2 = reinterpret_cast<__half2*>(out + (size_t)row * D_MODEL);
  o2[2 * t]     = __floats2half2_rn((v0.x - mean) * rstd * w0.x + b0.x,
                                    (v0.y - mean) * rstd * w0.y + b0.y);
  o2[2 * t + 1] = __floats2half2_rn((v0.z - mean) * rstd * w0.z + b0.z,
                                    (v0.w - mean) * rstd * w0.w + b0.w);
  o2[2 * (t + 128)]     = __floats2half2_rn((v1.x - mean) * rstd * w1.x + b1.x,
                                            (v1.y - mean) * rstd * w1.y + b1.y);
  o2[2 * (t + 128) + 1] = __floats2half2_rn((v1.z - mean) * rstd * w1.z + b1.z,
                                            (v1.w - mean) * rstd * w1.w + b1.w);
}

// -------------------- layernorm --------------------
__global__ __launch_bounds__(128) void ln_kernel(
    const float* __restrict__ in, const float* __restrict__ w,
    const float* __restrict__ b, __half* __restrict__ out) {
  int row = blockIdx.x;
  int t = threadIdx.x;
  const float4* ip = reinterpret_cast<const float4*>(in + (size_t)row * D_MODEL);
  float4 v0 = ip[t], v1 = ip[t + 128];
  float s  = v0.x + v0.y + v0.z + v0.w + v1.x + v1.y + v1.z + v1.w;
  float ss = v0.x*v0.x + v0.y*v0.y + v0.z*v0.z + v0.w*v0.w
           + v1.x*v1.x + v1.y*v1.y + v1.z*v1.z + v1.w*v1.w;
#pragma unroll
  for (int off = 16; off; off >>= 1) {
    s  += __shfl_xor_sync(0xffffffffu, s,  off);
    ss += __shfl_xor_sync(0xffffffffu, ss, off);
  }
  __shared__ float shs[4], shss[4];
  int wid = t >> 5;
  if ((t & 31) == 0) { shs[wid] = s; shss[wid] = ss; }
  __syncthreads();
  float tot  = shs[0] + shs[1] + shs[2] + shs[3];
  float tots = shss[0] + shss[1] + shss[2] + shss[3];
  float mean = tot * (1.0f / D_MODEL);
  float var  = tots * (1.0f / D_MODEL) - mean * mean;
  float rstd = rsqrtf(var + 1e-5f);
  const float4* wp = reinterpret_cast<const float4*>(w);
  const float4* bp = reinterpret_cast<const float4*>(b);
  float4 w0 = wp[t], w1 = wp[t + 128];
  float4 b0 = bp[t], b1 = bp[t + 128];
  __half2* o2 = reinterpret_cast<__half2*>(out + (size_t)row * D_MODEL);
  o2[2 * t]     = __floats2half2_rn((v0.x - mean) * rstd * w0.x + b0.x,
                                    (v0.y - mean) * rstd * w0.y + b0.y);
  o2[2 * t + 1] = __floats2half2_rn((v0.z - mean) * rstd * w0.z + b0.z,
                                    (v0.w - mean) * rstd * w0.w + b0.w);
  o2[2 * (t + 128)]     = __floats2half2_rn((v1.x - mean) * rstd * w1.x + b1.x,
                                            (v1.y - mean) * rstd * w1.y + b1.y);
  o2[2 * (t + 128) + 1] = __floats2half2_rn((v1.z - mean) * rstd * w1.z + b1.z,
                                            (v1.w - mean) * rstd * w1.w + b1.w);
}

// -------------------- FP16 tensor-core GEMM (128x128, warp 64x32) --------
#define KT        64
#define LDA_B     144
#define LDB_B     272
#define A_BYTES   (128 * LDA_B)
#define B_BYTES   (KT * LDB_B)
#define STAGE_B   (A_BYTES + B_BYTES)
#define NSTAGES   3
#define GEMM_SMEM (NSTAGES * STAGE_B)

template<bool GELU, bool ACCUM, bool OUTH, bool SWAP>
__global__ __launch_bounds__(256) void hgemm(
    const __half* __restrict__ A, const __half* __restrict__ B,
    const float* __restrict__ bias, void* __restrict__ Cv,
    int M, int K, int NB, int Nstore) {
  extern __shared__ __align__(16) char smem[];
  const uint32_t sm = (uint32_t)__cvta_generic_to_shared(smem);

  const int tid  = threadIdx.x;
  const int lane = tid & 31, warp = tid >> 5;
  const int wm = (warp >> 2) * 64;
  const int wn = (warp & 3) * 32;
  const int g = lane >> 2, t = lane & 3;
  const int brow = (SWAP ? blockIdx.x : blockIdx.y) * 128;
  const int bcol = (SWAP ? blockIdx.y : blockIdx.x) * 128;
  const uint32_t laneRow = lane & 15, laneHi = lane >> 4;

  float acc[16][4];
#pragma unroll
  for (int i = 0; i < 16; i++)
#pragma unroll
    for (int j = 0; j < 4; j++) acc[i][j] = 0.f;

  const int NT = K / KT;

  auto stage = [&](int tt) {
    const int k0 = tt * KT;
    const uint32_t sA = sm + (uint32_t)(tt % NSTAGES) * STAGE_B;
    const uint32_t sB = sA + A_BYTES;
    {
      int slot = tid;
#pragma unroll
      for (int i = 0; i < 4; i++) {
        int r = slot >> 3, ch = slot & 7;
        cp_async16(sA + (uint32_t)r * LDA_B + ch * 16,
                   A + (size_t)(brow + r) * K + k0 + ch * 8);
        slot += 256;
      }
    }
    {
      int slot = tid;
#pragma unroll
      for (int i = 0; i < 4; i++) {
        int r = slot >> 4, ch = slot & 15;
        cp_async16(sB + (uint32_t)r * LDB_B + ch * 16,
                   B + (size_t)(k0 + r) * NB + bcol + ch * 8);
        slot += 256;
      }
    }
    asm volatile("cp.async.commit_group;\n" ::: "memory");
  };

  stage(0);
  if (NT > 1) stage(1);

  for (int tt = 0; tt < NT; tt++) {
    if (tt + 1 < NT) {
      asm volatile("cp.async.wait_group 1;\n" ::: "memory");
    } else {
      asm volatile("cp.async.wait_group 0;\n" ::: "memory");
    }
    __syncthreads();
    if (tt + 2 < NT) stage(tt + 2);

    const uint32_t sA = sm + (uint32_t)(tt % NSTAGES) * STAGE_B;
    const uint32_t sB = sA + A_BYTES;

#pragma unroll
    for (int ik = 0; ik < 4; ik++) {
      uint32_t a[4][4];
#pragma unroll
      for (int im = 0; im < 4; im++)
        ldsm_x4(a[im], sA + (uint32_t)(wm + im * 16 + laneRow) * LDA_B
                          + ik * 32 + laneHi * 16);
      uint32_t b[4][2];
#pragma unroll
      for (int jp = 0; jp < 2; jp++) {
        uint32_t r[4];
        ldsm_x4_t(r, sB + (uint32_t)(ik * 16 + laneRow) * LDB_B
                        + (uint32_t)(wn + jp * 16 + laneHi * 8) * 2);
        b[2 * jp][0] = r[0]; b[2 * jp][1] = r[1];
        b[2 * jp + 1][0] = r[2]; b[2 * jp + 1][1] = r[3];
      }
#pragma unroll
      for (int im = 0; im < 4; im++)
#pragma unroll
        for (int jn = 0; jn < 4; jn++)
          mma_f16(acc[im * 4 + jn], a[im], b[jn][0], b[jn][1]);
    }
    __syncthreads();
  }

  float*  Cf = (float*)Cv;
  __half* Ch = (__half*)Cv;
#pragma unroll
  for (int im = 0; im < 4; im++) {
#pragma unroll
    for (int jn = 0; jn < 4; jn++) {
      const float* c = acc[im * 4 + jn];
      int r0 = brow + wm + im * 16 + g;
      int c0 = bcol + wn + jn * 8 + 2 * t;
#pragma unroll
      for (int u = 0; u < 4; u++) {
        int r = r0 + (u >> 1) * 8;
        int cc = c0 + (u & 1);
        if (cc < Nstore) {
          float val = c[u] + bias[cc];
          if (GELU) val = gelu_new(val);
          size_t idx = (size_t)r * Nstore + cc;
          if (OUTH) {
            Ch[idx] = __float2half(val);
          } else {
            if (ACCUM) val += Cf[idx];
            Cf[idx] = val;
          }
        }
      }
    }
  }
}

// -------------------- tensor-core flash attention --------------------
#define ATT_LD 144
__global__ __launch_bounds__(128) void attn_tc(
    const __half* __restrict__ qkv, __half* __restrict__ z) {
  const int b = blockIdx.z, h = blockIdx.y;
  const int q0 = (gridDim.x - 1 - blockIdx.x) * 64;
  const int tid = threadIdx.x;
  const int warp = tid >> 5, lane = tid & 31;
  const int g = lane >> 2, t = lane & 3;

  __shared__ __align__(16) __half sQ[64 * 72];
  __shared__ __align__(16) __half sK[2][64 * 72];
  __shared__ __align__(16) __half sV[2][64 * 72];
  const uint32_t qb = (uint32_t)__cvta_generic_to_shared(sQ);
  const uint32_t kb0 = (uint32_t)__cvta_generic_to_shared(sK[0]);
  const uint32_t kb1 = (uint32_t)__cvta_generic_to_shared(sK[1]);
  const uint32_t vb0 = (uint32_t)__cvta_generic_to_shared(sV[0]);
  const uint32_t vb1 = (uint32_t)__cvta_generic_to_shared(sV[1]);

  for (int slot = tid; slot < 512; slot += 128) {
    int r = slot >> 3, c = slot & 7;
    *reinterpret_cast<uint4*>(&sQ[r * 72 + c * 8]) =
      *reinterpret_cast<const uint4*>(
        qkv + (size_t)(b * S_LEN + q0 + r) * QKV_N + h * D_HEAD + c * 8);
  }
  __syncthreads();

  uint32_t qf[4][4];
#pragma unroll
  for (int ik = 0; ik < 4; ik++)
    ldsm_x4(qf[ik], qb + (uint32_t)(warp * 16 + (lane & 15)) * ATT_LD
                       + ik * 32 + (lane >> 4) * 16);

  const int row0 = q0 + warp * 16 + g;
  const int row1 = row0 + 8;

  float m0 = -INFINITY, m1 = -INFINITY, l0 = 0.f, l1 = 0.f;
  float oacc[8][4];
#pragma unroll
  for (int i = 0; i < 8; i++)
#pragma unroll
    for (int j = 0; j < 4; j++) oacc[i][j] = 0.f;

  const int ntiles = (q0 >> 6) + 1;

  auto stageKV = [&](int tile) {
    const int kt = tile * 64;
    const uint32_t kd = (tile & 1) ? kb1 : kb0;
    const uint32_t vd = (tile & 1) ? vb1 : vb0;
    for (int slot = tid; slot < 512; slot += 128) {
      int r = slot >> 3, c = slot & 7;
      const __half* src = qkv + (size_t)(b * S_LEN + kt + r) * QKV_N
                              + 1024 + h * D_HEAD + c * 8;
      cp_async16(kd + (uint32_t)r * ATT_LD + c * 16, src);
      cp_async16(vd + (uint32_t)r * ATT_LD + c * 16, src + 1024);
    }
    asm volatile("cp.async.commit_group;\n" ::: "memory");
  };

  stageKV(0);

  for (int tile = 0; tile < ntiles; tile++) {
    asm volatile("cp.async.wait_group 0;\n" ::: "memory");
    __syncthreads();
    if (tile + 1 < ntiles) stageKV(tile + 1);

    const uint32_t kd = (tile & 1) ? kb1 : kb0;
    const uint32_t vd = (tile & 1) ? vb1 : vb0;
    const int kt = tile * 64;

    float sacc[8][4];
#pragma unroll
    for (int j = 0; j < 8; j++) {
#pragma unroll
      for (int u = 0; u < 4; u++) sacc[j][u] = 0.f;
      uint32_t bk0[4], bk1[4];
      uint32_t base = kd + (uint32_t)(j * 8 + (lane & 7)) * ATT_LD + (lane >> 3) * 16;
      ldsm_x4(bk0, base);
      ldsm_x4(bk1, base + 64);
      mma_f16(sacc[j], qf[0], bk0[0], bk0[1]);
      mma_f16(sacc[j], qf[1], bk0[2], bk0[3]);
      mma_f16(sacc[j], qf[2], bk1[0], bk1[1]);
      mma_f16(sacc[j], qf[3], bk1[2], bk1[3]);
    }

    float tmx0 = -1e30f, tmx1 = -1e30f;
#pragma unroll
    for (int j = 0; j < 8; j++) {
      int kbase = kt + j * 8 + 2 * t;
      sacc[j][0] = (kbase     <= row0) ? sacc[j][0] * 0.125f : -1e30f;
      sacc[j][1] = (kbase + 1 <= row0) ? sacc[j][1] * 0.125f : -1e30f;
      sacc[j][2] = (kbase     <= row1) ? sacc[j][2] * 0.125f : -1e30f;
      sacc[j][3] = (kbase + 1 <= row1) ? sacc[j][3] * 0.125f : -1e30f;
      tmx0 = fmaxf(tmx0, fmaxf(sacc[j][0], sacc[j][1]));
      tmx1 = fmaxf(tmx1, fmaxf(sacc[j][2], sacc[j][3]));
    }
#pragma unroll
    for (int off = 1; off <= 2; off <<= 1) {
      tmx0 = fmaxf(tmx0, __shfl_xor_sync(0xffffffffu, tmx0, off));
      tmx1 = fmaxf(tmx1, __shfl_xor_sync(0xffffffffu, tmx1, off));
    }
    float mn0 = fmaxf(m0, tmx0), mn1 = fmaxf(m1, tmx1);
    float corr0 = __expf(m0 - mn0), corr1 = __expf(m1 - mn1);
    m0 = mn0; m1 = mn1;

    uint32_t pf[8][2];
    float sum0 = 0.f, sum1 = 0.f;
#pragma unroll
    for (int j = 0; j < 8; j++) {
      float p0 = __expf(sacc[j][0] - mn0);
      float p1 = __expf(sacc[j][1] - mn0);
      float p2 = __expf(sacc[j][2] - mn1);
      float p3 = __expf(sacc[j][3] - mn1);
      sum0 += p0 + p1; sum1 += p2 + p3;
      __half2 h01 = __floats2half2_rn(p0, p1);
      __half2 h23 = __floats2half2_rn(p2, p3);
      pf[j][0] = *reinterpret_cast<uint32_t*>(&h01);
      pf[j][1] = *reinterpret_cast<uint32_t*>(&h23);
    }
#pragma unroll
    for (int off = 1; off <= 2; off <<= 1) {
      sum0 += __shfl_xor_sync(0xffffffffu, sum0, off);
      sum1 += __shfl_xor_sync(0xffffffffu, sum1, off);
    }
    l0 = l0 * corr0 + sum0;
    l1 = l1 * corr1 + sum1;
#pragma unroll
    for (int np = 0; np < 8; np++) {
      oacc[np][0] *= corr0; oacc[np][1] *= corr0;
      oacc[np][2] *= corr1; oacc[np][3] *= corr1;
    }

#pragma unroll
    for (int kk = 0; kk < 4; kk++) {
      uint32_t a[4] = { pf[2 * kk][0], pf[2 * kk][1],
                        pf[2 * kk + 1][0], pf[2 * kk + 1][1] };
#pragma unroll
      for (int np = 0; np < 4; np++) {
        uint32_t r[4];
        ldsm_x4_t(r, vd + (uint32_t)(kk * 16 + (lane & 15)) * ATT_LD
                        + np * 32 + (lane >> 4) * 16);
        mma_f16(oacc[2 * np], a, r[0], r[1]);
        mma_f16(oacc[2 * np + 1], a, r[2], r[3]);
      }
    }
    __syncthreads();
  }

  const float inv0 = 1.0f / l0, inv1 = 1.0f / l1;
#pragma unroll
  for (int np = 0; np < 8; np++) {
    int col = h * D_HEAD + np * 8 + 2 * t;
    __half2 lo = __floats2half2_rn(oacc[np][0] * inv0, oacc[np][1] * inv0);
    __half2 hi = __floats2half2_rn(oacc[np][2] * inv1, oacc[np][3] * inv1);
    *reinterpret_cast<__half2*>(&z[(size_t)(b * S_LEN + row0) * D_MODEL + col]) = lo;
    *reinterpret_cast<__half2*>(&z[(size_t)(b * S_LEN + row1) * D_MODEL + col]) = hi;
  }
}

// -------------------- driver --------------------
template<bool GELU, bool ACCUM, bool OUTH, bool SWAP>
static void launch_hgemm(const __half* A, const __half* B, const float* bias,
                         void* C, int M, int K, int NB, int Nstore) {
  cudaFuncSetAttribute(hgemm<GELU, ACCUM, OUTH, SWAP>,
                       cudaFuncAttributeMaxDynamicSharedMemorySize, GEMM_SMEM);
  dim3 grid = SWAP ? dim3(M / 128, NB / 128) : dim3(NB / 128, M / 128);
  hgemm<GELU, ACCUM, OUTH, SWAP><<<grid, 256, GEMM_SMEM>>>(A, B, bias, C, M, K, NB, Nstore);
}

extern "C" void kernel_launch(void* const* d_in, const int* in_sizes, int n_in,
                              void* d_out, int out_size) {
  const int*   tokens = (const int*)  d_in[0];
  const float* W_E    = (const float*)d_in[1];
  const float* W_pos  = (const float*)d_in[2];
  const float* ln1_w  = (const float*)d_in[3];
  const float* ln1_b  = (const float*)d_in[4];
  const float* W_Q    = (const float*)d_in[5];
  const float* b_Q    = (const float*)d_in[6];
  const float* W_K    = (const float*)d_in[7];
  const float* b_K    = (const float*)d_in[8];
  const float* W_V    = (const float*)d_in[9];
  const float* b_V    = (const float*)d_in[10];
  const float* W_O    = (const float*)d_in[11];
  const float* b_O    = (const float*)d_in[12];
  const float* ln2_w  = (const float*)d_in[13];
  const float* ln2_b  = (const float*)d_in[14];
  const float* W_in   = (const float*)d_in[15];
  const float* b_in   = (const float*)d_in[16];
  const float* W_out  = (const float*)d_in[17];
  const float* b_out  = (const float*)d_in[18];
  const float* lnf_w  = (const float*)d_in[19];
  const float* lnf_b  = (const float*)d_in[20];
  const float* W_U    = (const float*)d_in[21];
  const float* b_U    = (const float*)d_in[22];
  float* out = (float*)d_out;

  float *resid, *bqkv;
  __half *xh, *qkvh, *zh, *hh, *wqkv, *wo, *win, *wout, *wu;
  cudaGetSymbolAddress((void**)&resid, g_resid);
  cudaGetSymbolAddress((void**)&xh,    g_xh);
  cudaGetSymbolAddress((void**)&qkvh,  g_qkvh);
  cudaGetSymbolAddress((void**)&zh,    g_zh);
  cudaGetSymbolAddress((void**)&hh,    g_hh);
  cudaGetSymbolAddress((void**)&wqkv,  g_wqkv);
  cudaGetSymbolAddress((void**)&bqkv,  g_bqkv);
  cudaGetSymbolAddress((void**)&wo,    g_wo);
  cudaGetSymbolAddress((void**)&win,   g_win);
  cudaGetSymbolAddress((void**)&wout,  g_wout);
  cudaGetSymbolAddress((void**)&wu,    g_wu);

  // one merged conversion kernel (vocab | qkv | wo/win/wout)
  conv_all<<<TOTAL_UNITS / 256, 256>>>(W_U, W_Q, W_K, W_V, W_O, W_in, W_out,
                                       wu, wqkv, wo, win, wout);
  pack_bias_qkv<<<(N_LAYERS * QKV_N) / 256, 256>>>(b_Q, b_K, b_V, bqkv);

  dim3 gA(S_LEN / 64, N_HEADS, 2);

  for (int l = 0; l < N_LAYERS; l++) {
    size_t w1 = (size_t)l * D_MODEL * D_MODEL;
    size_t w2 = (size_t)l * D_MODEL * D_MLP;
    const float* l1w = ln1_w + (size_t)l * D_MODEL;
    const float* l1b = ln1_b + (size_t)l * D_MODEL;
    const float* l2w = ln2_w + (size_t)l * D_MODEL;
    const float* l2b = ln2_b + (size_t)l * D_MODEL;

    if (l == 0) {
      embed_ln_kernel<<<N_TOKENS, 128>>>(tokens, W_E, W_pos, l1w, l1b, resid, xh);
    } else {
      ln_kernel<<<N_TOKENS, 128>>>(resid, l1w, l1b, xh);
    }
    launch_hgemm<false, false, true, false>(xh, wqkv + (size_t)l * D_MODEL * QKV_N,
                                            bqkv + (size_t)l * QKV_N, qkvh,
                                            N_TOKENS, D_MODEL, QKV_N, QKV_N);
    attn_tc<<<gA, 128>>>(qkvh, zh);
    launch_hgemm<false, true, false, false>(zh, wo + w1, b_O + (size_t)l * D_MODEL, resid,
                                            N_TOKENS, D_MODEL, D_MODEL, D_MODEL);
    ln_kernel<<<N_TOKENS, 128>>>(resid, l2w, l2b, xh);
    launch_hgemm<true, false, true, false>(xh, win + w2, b_in + (size_t)l * D_MLP, hh,
                                           N_TOKENS, D_MODEL, D_MLP, D_MLP);
    launch_hgemm<false, true, false, false>(hh, wout + w2, b_out + (size_t)l * D_MODEL, resid,
                                            N_TOKENS, D_MLP, D_MODEL, D_MODEL);
  }

  ln_kernel<<<N_TOKENS, 128>>>(resid, lnf_w, lnf_b, xh);
  launch_hgemm<false, false, false, true>(xh, wu, b_U, out,
                                          N_TOKENS, D_MODEL, N_VOCAB_PAD, N_VOCAB);
}

// round 17
// speedup vs baseline: 1.1056x; 1.0073x over previous
#include <cuda_runtime.h>
#include <cuda_fp16.h>
#include <cstdint>
#include <math.h>

#define S_LEN    2048
#define D_MODEL  1024
#define N_HEADS  16
#define D_HEAD   64
#define D_MLP    4096
#define N_LAYERS 4
#define N_VOCAB  50257
#define N_VOCAB_PAD 50304   // 393*128
#define N_TOKENS 4096
#define QKV_N    3072

// -------------------- scratch --------------------
__device__ float  g_resid[N_TOKENS * D_MODEL];
__device__ __half g_xh   [N_TOKENS * D_MODEL];
__device__ __half g_qkvh [N_TOKENS * QKV_N];
__device__ __half g_zh   [N_TOKENS * D_MODEL];
__device__ __half g_hh   [N_TOKENS * D_MLP];
__device__ __half g_wqkv [N_LAYERS * D_MODEL * QKV_N];
__device__ float  g_bqkv [N_LAYERS * QKV_N];
__device__ __half g_wo   [N_LAYERS * D_MODEL * D_MODEL];
__device__ __half g_win  [N_LAYERS * D_MODEL * D_MLP];
__device__ __half g_wout [N_LAYERS * D_MLP * D_MODEL];
__device__ __half g_wu   [D_MODEL * N_VOCAB_PAD];

#define WO_ELEMS    (N_LAYERS * D_MODEL * D_MODEL)
#define WIN_ELEMS   (N_LAYERS * D_MODEL * D_MLP)
#define WOUT_ELEMS  (N_LAYERS * D_MLP * D_MODEL)
#define VOCAB_UNITS (D_MODEL * N_VOCAB_PAD / 8)
#define QKV_UNITS   (N_LAYERS * D_MODEL * QKV_N / 8)
#define WO_UNITS    (WO_ELEMS / 8)
#define WIN_UNITS   (WIN_ELEMS / 8)
#define WOUT_UNITS  (WOUT_ELEMS / 8)
#define FLAT3_UNITS (WO_UNITS + WIN_UNITS + WOUT_UNITS)
#define TOTAL_UNITS (VOCAB_UNITS + QKV_UNITS + FLAT3_UNITS)

// -------------------- helpers --------------------
__device__ __forceinline__ float gelu_new(float x) {
  float u = 0.7978845608028654f * (x + 0.044715f * x * x * x);
  return 0.5f * x * (1.0f + tanhf(u));
}
__device__ __forceinline__ void ldsm_x4(uint32_t (&r)[4], uint32_t addr) {
  asm volatile("ldmatrix.sync.aligned.m8n8.x4.shared.b16 {%0,%1,%2,%3}, [%4];"
    : "=r"(r[0]), "=r"(r[1]), "=r"(r[2]), "=r"(r[3]) : "r"(addr));
}
__device__ __forceinline__ void ldsm_x4_t(uint32_t (&r)[4], uint32_t addr) {
  asm volatile("ldmatrix.sync.aligned.m8n8.x4.trans.shared.b16 {%0,%1,%2,%3}, [%4];"
    : "=r"(r[0]), "=r"(r[1]), "=r"(r[2]), "=r"(r[3]) : "r"(addr));
}
__device__ __forceinline__ void mma_f16(float (&c)[4], const uint32_t (&a)[4],
                                        const uint32_t b0, const uint32_t b1) {
  asm volatile("mma.sync.aligned.m16n8k16.row.col.f32.f16.f16.f32 "
    "{%0,%1,%2,%3}, {%4,%5,%6,%7}, {%8,%9}, {%0,%1,%2,%3};"
    : "+f"(c[0]), "+f"(c[1]), "+f"(c[2]), "+f"(c[3])
    : "r"(a[0]), "r"(a[1]), "r"(a[2]), "r"(a[3]), "r"(b0), "r"(b1));
}
__device__ __forceinline__ void cp_async16(uint32_t dst, const void* src) {
  asm volatile("cp.async.cg.shared.global [%0], [%1], 16;\n" :: "r"(dst), "l"(src));
}
__device__ __forceinline__ uint4 pack8(const float4 a, const float4 b) {
  __half2 h0 = __floats2half2_rn(a.x, a.y);
  __half2 h1 = __floats2half2_rn(a.z, a.w);
  __half2 h2 = __floats2half2_rn(b.x, b.y);
  __half2 h3 = __floats2half2_rn(b.z, b.w);
  uint4 r;
  r.x = *reinterpret_cast<uint32_t*>(&h0);
  r.y = *reinterpret_cast<uint32_t*>(&h1);
  r.z = *reinterpret_cast<uint32_t*>(&h2);
  r.w = *reinterpret_cast<uint32_t*>(&h3);
  return r;
}

// -------------------- merged weight conversion --------------------
__global__ __launch_bounds__(256) void conv_all(
    const float* __restrict__ WU,
    const float* __restrict__ WQ, const float* __restrict__ WK,
    const float* __restrict__ WV,
    const float* __restrict__ WO, const float* __restrict__ WIN,
    const float* __restrict__ WOUT,
    __half* __restrict__ wu, __half* __restrict__ wqkv,
    __half* __restrict__ wo, __half* __restrict__ win,
    __half* __restrict__ wout) {
  size_t u = (size_t)blockIdx.x * 256 + threadIdx.x;
  if (u < VOCAB_UNITS) {
    int k = (int)(u / (N_VOCAB_PAD / 8));
    int n = (int)(u % (N_VOCAB_PAD / 8)) * 8;
    const float* row = WU + (size_t)k * N_VOCAB;
    float f[8];
#pragma unroll
    for (int i = 0; i < 8; i++) {
      int c = n + i;
      f[i] = (c < N_VOCAB) ? __ldg(row + c) : 0.f;
    }
    float4 a = make_float4(f[0], f[1], f[2], f[3]);
    float4 b = make_float4(f[4], f[5], f[6], f[7]);
    *reinterpret_cast<uint4*>(wu + (size_t)k * N_VOCAB_PAD + n) = pack8(a, b);
    return;
  }
  u -= VOCAB_UNITS;
  if (u < QKV_UNITS) {
    size_t i8 = u * 8;
    int n = (int)(i8 % QKV_N);
    size_t lk = i8 / QKV_N;
    int k = (int)(lk % D_MODEL);
    int l = (int)(lk / D_MODEL);
    int which = n >> 10, nn = n & 1023;
    int h = nn >> 6, dh = nn & 63;
    const float* W = (which == 0) ? WQ : ((which == 1) ? WK : WV);
    const float* src = W + (((size_t)l * N_HEADS + h) * D_MODEL + k) * D_HEAD + dh;
    float4 a = *reinterpret_cast<const float4*>(src);
    float4 b = *reinterpret_cast<const float4*>(src + 4);
    *reinterpret_cast<uint4*>(wqkv + i8) = pack8(a, b);
    return;
  }
  u -= QKV_UNITS;
  const float* src;
  __half* dst;
  size_t off;
  if (u < WO_UNITS) {
    src = WO; dst = wo; off = u * 8;
  } else if (u < WO_UNITS + WIN_UNITS) {
    src = WIN; dst = win; off = (u - WO_UNITS) * 8;
  } else {
    src = WOUT; dst = wout; off = (u - WO_UNITS - WIN_UNITS) * 8;
  }
  float4 a = *reinterpret_cast<const float4*>(src + off);
  float4 b = *reinterpret_cast<const float4*>(src + off + 4);
  *reinterpret_cast<uint4*>(dst + off) = pack8(a, b);
}

__global__ __launch_bounds__(256) void pack_bias_qkv(
    const float* __restrict__ bq, const float* __restrict__ bk,
    const float* __restrict__ bv, float* __restrict__ out) {
  int i = blockIdx.x * 256 + threadIdx.x;
  int n = i % QKV_N, l = i / QKV_N;
  const float* s = (n < 1024) ? bq : ((n < 2048) ? bk : bv);
  out[i] = s[l * 1024 + (n & 1023)];
}

// -------------------- fused embed + layer-0 LN1 --------------------
__global__ __launch_bounds__(128) void embed_ln_kernel(
    const int* __restrict__ tok, const float* __restrict__ WE,
    const float* __restrict__ Wp, const float* __restrict__ w,
    const float* __restrict__ b, float* __restrict__ resid,
    __half* __restrict__ out) {
  int row = blockIdx.x;
  int s = row & (S_LEN - 1);
  int t = threadIdx.x;
  int token = tok[row];
  const float4* we = reinterpret_cast<const float4*>(WE + (size_t)token * D_MODEL);
  const float4* wpp = reinterpret_cast<const float4*>(Wp + (size_t)s * D_MODEL);
  float4 e0 = we[t], e1 = we[t + 128];
  float4 p0 = wpp[t], p1 = wpp[t + 128];
  float4 v0, v1;
  v0.x = e0.x + p0.x; v0.y = e0.y + p0.y; v0.z = e0.z + p0.z; v0.w = e0.w + p0.w;
  v1.x = e1.x + p1.x; v1.y = e1.y + p1.y; v1.z = e1.z + p1.z; v1.w = e1.w + p1.w;
  float4* r = reinterpret_cast<float4*>(resid + (size_t)row * D_MODEL);
  r[t] = v0;
  r[t + 128] = v1;
  float sm  = v0.x + v0.y + v0.z + v0.w + v1.x + v1.y + v1.z + v1.w;
  float ss = v0.x*v0.x + v0.y*v0.y + v0.z*v0.z + v0.w*v0.w
           + v1.x*v1.x + v1.y*v1.y + v1.z*v1.z + v1.w*v1.w;
#pragma unroll
  for (int off = 16; off; off >>= 1) {
    sm += __shfl_xor_sync(0xffffffffu, sm, off);
    ss += __shfl_xor_sync(0xffffffffu, ss, off);
  }
  __shared__ float shs[4], shss[4];
  int wid = t >> 5;
  if ((t & 31) == 0) { shs[wid] = sm; shss[wid] = ss; }
  __syncthreads();
  float tot  = shs[0] + shs[1] + shs[2] + shs[3];
  float tots = shss[0] + shss[1] + shss[2] + shss[3];
  float mean = tot * (1.0f / D_MODEL);
  float var  = tots * (1.0f / D_MODEL) - mean * mean;
  float rstd = rsqrtf(var + 1e-5f);
  const float4* wp = reinterpret_cast<const float4*>(w);
  const float4* bp = reinterpret_cast<const float4*>(b);
  float4 w0 = wp[t], w1 = wp[t + 128];
  float4 b0 = bp[t], b1 = bp[t + 128];
  __half2* o2 = reinterpret_cast<__half2*>(out + (size_t)row * D_MODEL);
  o2[2 * t]     = __floats2half2_rn((v0.x - mean) * rstd * w0.x + b0.x,
                                    (v0.y - mean) * rstd * w0.y + b0.y);
  o2[2 * t + 1] = __floats2half2_rn((v0.z - mean) * rstd * w0.z + b0.z,
                                    (v0.w - mean) * rstd * w0.w + b0.w);
  o2[2 * (t + 128)]     = __floats2half2_rn((v1.x - mean) * rstd * w1.x + b1.x,
                                            (v1.y - mean) * rstd * w1.y + b1.y);
  o2[2 * (t + 128) + 1] = __floats2half2_rn((v1.z - mean) * rstd * w1.z + b1.z,
                                            (v1.w - mean) * rstd * w1.w + b1.w);
}

// -------------------- layernorm --------------------
__global__ __launch_bounds__(128) void ln_kernel(
    const float* __restrict__ in, const float* __restrict__ w,
    const float* __restrict__ b, __half* __restrict__ out) {
  int row = blockIdx.x;
  int t = threadIdx.x;
  const float4* ip = reinterpret_cast<const float4*>(in + (size_t)row * D_MODEL);
  float4 v0 = ip[t], v1 = ip[t + 128];
  float s  = v0.x + v0.y + v0.z + v0.w + v1.x + v1.y + v1.z + v1.w;
  float ss = v0.x*v0.x + v0.y*v0.y + v0.z*v0.z + v0.w*v0.w
           + v1.x*v1.x + v1.y*v1.y + v1.z*v1.z + v1.w*v1.w;
#pragma unroll
  for (int off = 16; off; off >>= 1) {
    s  += __shfl_xor_sync(0xffffffffu, s,  off);
    ss += __shfl_xor_sync(0xffffffffu, ss, off);
  }
  __shared__ float shs[4], shss[4];
  int wid = t >> 5;
  if ((t & 31) == 0) { shs[wid] = s; shss[wid] = ss; }
  __syncthreads();
  float tot  = shs[0] + shs[1] + shs[2] + shs[3];
  float tots = shss[0] + shss[1] + shss[2] + shss[3];
  float mean = tot * (1.0f / D_MODEL);
  float var  = tots * (1.0f / D_MODEL) - mean * mean;
  float rstd = rsqrtf(var + 1e-5f);
  const float4* wp = reinterpret_cast<const float4*>(w);
  const float4* bp = reinterpret_cast<const float4*>(b);
  float4 w0 = wp[t], w1 = wp[t + 128];
  float4 b0 = bp[t], b1 = bp[t + 128];
  __half2* o2 = reinterpret_cast<__half2*>(out + (size_t)row * D_MODEL);
  o2[2 * t]     = __floats2half2_rn((v0.x - mean) * rstd * w0.x + b0.x,
                                    (v0.y - mean) * rstd * w0.y + b0.y);
  o2[2 * t + 1] = __floats2half2_rn((v0.z - mean) * rstd * w0.z + b0.z,
                                    (v0.w - mean) * rstd * w0.w + b0.w);
  o2[2 * (t + 128)]     = __floats2half2_rn((v1.x - mean) * rstd * w1.x + b1.x,
                                            (v1.y - mean) * rstd * w1.y + b1.y);
  o2[2 * (t + 128) + 1] = __floats2half2_rn((v1.z - mean) * rstd * w1.z + b1.z,
                                            (v1.w - mean) * rstd * w1.w + b1.w);
}

// -------------------- FP16 tensor-core GEMM (128x128, warp 64x32) --------
// ONE barrier per k-tile: the leading sync (after wait_group) also separates
// compute(tt-1) readers from stage(tt+2) writers (slot (tt+2)%3 == (tt-1)%3).
#define KT        64
#define LDA_B     144
#define LDB_B     272
#define A_BYTES   (128 * LDA_B)
#define B_BYTES   (KT * LDB_B)
#define STAGE_B   (A_BYTES + B_BYTES)
#define NSTAGES   3
#define GEMM_SMEM (NSTAGES * STAGE_B)

template<bool GELU, bool ACCUM, bool OUTH, bool SWAP>
__global__ __launch_bounds__(256) void hgemm(
    const __half* __restrict__ A, const __half* __restrict__ B,
    const float* __restrict__ bias, void* __restrict__ Cv,
    int M, int K, int NB, int Nstore) {
  extern __shared__ __align__(16) char smem[];
  const uint32_t sm = (uint32_t)__cvta_generic_to_shared(smem);

  const int tid  = threadIdx.x;
  const int lane = tid & 31, warp = tid >> 5;
  const int wm = (warp >> 2) * 64;
  const int wn = (warp & 3) * 32;
  const int g = lane >> 2, t = lane & 3;
  const int brow = (SWAP ? blockIdx.x : blockIdx.y) * 128;
  const int bcol = (SWAP ? blockIdx.y : blockIdx.x) * 128;
  const uint32_t laneRow = lane & 15, laneHi = lane >> 4;

  float acc[16][4];
#pragma unroll
  for (int i = 0; i < 16; i++)
#pragma unroll
    for (int j = 0; j < 4; j++) acc[i][j] = 0.f;

  const int NT = K / KT;

  auto stage = [&](int tt) {
    const int k0 = tt * KT;
    const uint32_t sA = sm + (uint32_t)(tt % NSTAGES) * STAGE_B;
    const uint32_t sB = sA + A_BYTES;
    {
      int slot = tid;
#pragma unroll
      for (int i = 0; i < 4; i++) {
        int r = slot >> 3, ch = slot & 7;
        cp_async16(sA + (uint32_t)r * LDA_B + ch * 16,
                   A + (size_t)(brow + r) * K + k0 + ch * 8);
        slot += 256;
      }
    }
    {
      int slot = tid;
#pragma unroll
      for (int i = 0; i < 4; i++) {
        int r = slot >> 4, ch = slot & 15;
        cp_async16(sB + (uint32_t)r * LDB_B + ch * 16,
                   B + (size_t)(k0 + r) * NB + bcol + ch * 8);
        slot += 256;
      }
    }
    asm volatile("cp.async.commit_group;\n" ::: "memory");
  };

  stage(0);
  if (NT > 1) stage(1);

  for (int tt = 0; tt < NT; tt++) {
    if (tt + 1 < NT) {
      asm volatile("cp.async.wait_group 1;\n" ::: "memory");
    } else {
      asm volatile("cp.async.wait_group 0;\n" ::: "memory");
    }
    __syncthreads();   // single barrier: publishes stage(tt), protects slot reuse
    if (tt + 2 < NT) stage(tt + 2);

    const uint32_t sA = sm + (uint32_t)(tt % NSTAGES) * STAGE_B;
    const uint32_t sB = sA + A_BYTES;

#pragma unroll
    for (int ik = 0; ik < 4; ik++) {
      uint32_t a[4][4];
#pragma unroll
      for (int im = 0; im < 4; im++)
        ldsm_x4(a[im], sA + (uint32_t)(wm + im * 16 + laneRow) * LDA_B
                          + ik * 32 + laneHi * 16);
      uint32_t b[4][2];
#pragma unroll
      for (int jp = 0; jp < 2; jp++) {
        uint32_t r[4];
        ldsm_x4_t(r, sB + (uint32_t)(ik * 16 + laneRow) * LDB_B
                        + (uint32_t)(wn + jp * 16 + laneHi * 8) * 2);
        b[2 * jp][0] = r[0]; b[2 * jp][1] = r[1];
        b[2 * jp + 1][0] = r[2]; b[2 * jp + 1][1] = r[3];
      }
#pragma unroll
      for (int im = 0; im < 4; im++)
#pragma unroll
        for (int jn = 0; jn < 4; jn++)
          mma_f16(acc[im * 4 + jn], a[im], b[jn][0], b[jn][1]);
    }
    // no trailing __syncthreads: next iteration's leading barrier covers reuse
  }

  float*  Cf = (float*)Cv;
  __half* Ch = (__half*)Cv;
#pragma unroll
  for (int im = 0; im < 4; im++) {
#pragma unroll
    for (int jn = 0; jn < 4; jn++) {
      const float* c = acc[im * 4 + jn];
      int r0 = brow + wm + im * 16 + g;
      int c0 = bcol + wn + jn * 8 + 2 * t;
#pragma unroll
      for (int u = 0; u < 4; u++) {
        int r = r0 + (u >> 1) * 8;
        int cc = c0 + (u & 1);
        if (cc < Nstore) {
          float val = c[u] + bias[cc];
          if (GELU) val = gelu_new(val);
          size_t idx = (size_t)r * Nstore + cc;
          if (OUTH) {
            Ch[idx] = __float2half(val);
          } else {
            if (ACCUM) val += Cf[idx];
            Cf[idx] = val;
          }
        }
      }
    }
  }
}

// -------------------- tensor-core flash attention --------------------
#define ATT_LD 144
__global__ __launch_bounds__(128) void attn_tc(
    const __half* __restrict__ qkv, __half* __restrict__ z) {
  const int b = blockIdx.z, h = blockIdx.y;
  const int q0 = (gridDim.x - 1 - blockIdx.x) * 64;
  const int tid = threadIdx.x;
  const int warp = tid >> 5, lane = tid & 31;
  const int g = lane >> 2, t = lane & 3;

  __shared__ __align__(16) __half sQ[64 * 72];
  __shared__ __align__(16) __half sK[2][64 * 72];
  __shared__ __align__(16) __half sV[2][64 * 72];
  const uint32_t qb = (uint32_t)__cvta_generic_to_shared(sQ);
  const uint32_t kb0 = (uint32_t)__cvta_generic_to_shared(sK[0]);
  const uint32_t kb1 = (uint32_t)__cvta_generic_to_shared(sK[1]);
  const uint32_t vb0 = (uint32_t)__cvta_generic_to_shared(sV[0]);
  const uint32_t vb1 = (uint32_t)__cvta_generic_to_shared(sV[1]);

  for (int slot = tid; slot < 512; slot += 128) {
    int r = slot >> 3, c = slot & 7;
    *reinterpret_cast<uint4*>(&sQ[r * 72 + c * 8]) =
      *reinterpret_cast<const uint4*>(
        qkv + (size_t)(b * S_LEN + q0 + r) * QKV_N + h * D_HEAD + c * 8);
  }
  __syncthreads();

  uint32_t qf[4][4];
#pragma unroll
  for (int ik = 0; ik < 4; ik++)
    ldsm_x4(qf[ik], qb + (uint32_t)(warp * 16 + (lane & 15)) * ATT_LD
                       + ik * 32 + (lane >> 4) * 16);

  const int row0 = q0 + warp * 16 + g;
  const int row1 = row0 + 8;

  float m0 = -INFINITY, m1 = -INFINITY, l0 = 0.f, l1 = 0.f;
  float oacc[8][4];
#pragma unroll
  for (int i = 0; i < 8; i++)
#pragma unroll
    for (int j = 0; j < 4; j++) oacc[i][j] = 0.f;

  const int ntiles = (q0 >> 6) + 1;

  auto stageKV = [&](int tile) {
    const int kt = tile * 64;
    const uint32_t kd = (tile & 1) ? kb1 : kb0;
    const uint32_t vd = (tile & 1) ? vb1 : vb0;
    for (int slot = tid; slot < 512; slot += 128) {
      int r = slot >> 3, c = slot & 7;
      const __half* src = qkv + (size_t)(b * S_LEN + kt + r) * QKV_N
                              + 1024 + h * D_HEAD + c * 8;
      cp_async16(kd + (uint32_t)r * ATT_LD + c * 16, src);
      cp_async16(vd + (uint32_t)r * ATT_LD + c * 16, src + 1024);
    }
    asm volatile("cp.async.commit_group;\n" ::: "memory");
  };

  stageKV(0);

  for (int tile = 0; tile < ntiles; tile++) {
    asm volatile("cp.async.wait_group 0;\n" ::: "memory");
    __syncthreads();   // single barrier per tile (covers buffer reuse too)
    if (tile + 1 < ntiles) stageKV(tile + 1);

    const uint32_t kd = (tile & 1) ? kb1 : kb0;
    const uint32_t vd = (tile & 1) ? vb1 : vb0;
    const int kt = tile * 64;

    float sacc[8][4];
#pragma unroll
    for (int j = 0; j < 8; j++) {
#pragma unroll
      for (int u = 0; u < 4; u++) sacc[j][u] = 0.f;
      uint32_t bk0[4], bk1[4];
      uint32_t base = kd + (uint32_t)(j * 8 + (lane & 7)) * ATT_LD + (lane >> 3) * 16;
      ldsm_x4(bk0, base);
      ldsm_x4(bk1, base + 64);
      mma_f16(sacc[j], qf[0], bk0[0], bk0[1]);
      mma_f16(sacc[j], qf[1], bk0[2], bk0[3]);
      mma_f16(sacc[j], qf[2], bk1[0], bk1[1]);
      mma_f16(sacc[j], qf[3], bk1[2], bk1[3]);
    }

    float tmx0 = -1e30f, tmx1 = -1e30f;
#pragma unroll
    for (int j = 0; j < 8; j++) {
      int kbase = kt + j * 8 + 2 * t;
      sacc[j][0] = (kbase     <= row0) ? sacc[j][0] * 0.125f : -1e30f;
      sacc[j][1] = (kbase + 1 <= row0) ? sacc[j][1] * 0.125f : -1e30f;
      sacc[j][2] = (kbase     <= row1) ? sacc[j][2] * 0.125f : -1e30f;
      sacc[j][3] = (kbase + 1 <= row1) ? sacc[j][3] * 0.125f : -1e30f;
      tmx0 = fmaxf(tmx0, fmaxf(sacc[j][0], sacc[j][1]));
      tmx1 = fmaxf(tmx1, fmaxf(sacc[j][2], sacc[j][3]));
    }
#pragma unroll
    for (int off = 1; off <= 2; off <<= 1) {
      tmx0 = fmaxf(tmx0, __shfl_xor_sync(0xffffffffu, tmx0, off));
      tmx1 = fmaxf(tmx1, __shfl_xor_sync(0xffffffffu, tmx1, off));
    }
    float mn0 = fmaxf(m0, tmx0), mn1 = fmaxf(m1, tmx1);
    float corr0 = __expf(m0 - mn0), corr1 = __expf(m1 - mn1);
    m0 = mn0; m1 = mn1;

    uint32_t pf[8][2];
    float sum0 = 0.f, sum1 = 0.f;
#pragma unroll
    for (int j = 0; j < 8; j++) {
      float p0 = __expf(sacc[j][0] - mn0);
      float p1 = __expf(sacc[j][1] - mn0);
      float p2 = __expf(sacc[j][2] - mn1);
      float p3 = __expf(sacc[j][3] - mn1);
      sum0 += p0 + p1; sum1 += p2 + p3;
      __half2 h01 = __floats2half2_rn(p0, p1);
      __half2 h23 = __floats2half2_rn(p2, p3);
      pf[j][0] = *reinterpret_cast<uint32_t*>(&h01);
      pf[j][1] = *reinterpret_cast<uint32_t*>(&h23);
    }
#pragma unroll
    for (int off = 1; off <= 2; off <<= 1) {
      sum0 += __shfl_xor_sync(0xffffffffu, sum0, off);
      sum1 += __shfl_xor_sync(0xffffffffu, sum1, off);
    }
    l0 = l0 * corr0 + sum0;
    l1 = l1 * corr1 + sum1;
#pragma unroll
    for (int np = 0; np < 8; np++) {
      oacc[np][0] *= corr0; oacc[np][1] *= corr0;
      oacc[np][2] *= corr1; oacc[np][3] *= corr1;
    }

#pragma unroll
    for (int kk = 0; kk < 4; kk++) {
      uint32_t a[4] = { pf[2 * kk][0], pf[2 * kk][1],
                        pf[2 * kk + 1][0], pf[2 * kk + 1][1] };
#pragma unroll
      for (int np = 0; np < 4; np++) {
        uint32_t r[4];
        ldsm_x4_t(r, vd + (uint32_t)(kk * 16 + (lane & 15)) * ATT_LD
                        + np * 32 + (lane >> 4) * 16);
        mma_f16(oacc[2 * np], a, r[0], r[1]);
        mma_f16(oacc[2 * np + 1], a, r[2], r[3]);
      }
    }
    // no trailing __syncthreads
  }

  const float inv0 = 1.0f / l0, inv1 = 1.0f / l1;
#pragma unroll
  for (int np = 0; np < 8; np++) {
    int col = h * D_HEAD + np * 8 + 2 * t;
    __half2 lo = __floats2half2_rn(oacc[np][0] * inv0, oacc[np][1] * inv0);
    __half2 hi = __floats2half2_rn(oacc[np][2] * inv1, oacc[np][3] * inv1);
    *reinterpret_cast<__half2*>(&z[(size_t)(b * S_LEN + row0) * D_MODEL + col]) = lo;
    *reinterpret_cast<__half2*>(&z[(size_t)(b * S_LEN + row1) * D_MODEL + col]) = hi;
  }
}

// -------------------- driver --------------------
template<bool GELU, bool ACCUM, bool OUTH, bool SWAP>
static void launch_hgemm(const __half* A, const __half* B, const float* bias,
                         void* C, int M, int K, int NB, int Nstore) {
  cudaFuncSetAttribute(hgemm<GELU, ACCUM, OUTH, SWAP>,
                       cudaFuncAttributeMaxDynamicSharedMemorySize, GEMM_SMEM);
  dim3 grid = SWAP ? dim3(M / 128, NB / 128) : dim3(NB / 128, M / 128);
  hgemm<GELU, ACCUM, OUTH, SWAP><<<grid, 256, GEMM_SMEM>>>(A, B, bias, C, M, K, NB, Nstore);
}

extern "C" void kernel_launch(void* const* d_in, const int* in_sizes, int n_in,
                              void* d_out, int out_size) {
  const int*   tokens = (const int*)  d_in[0];
  const float* W_E    = (const float*)d_in[1];
  const float* W_pos  = (const float*)d_in[2];
  const float* ln1_w  = (const float*)d_in[3];
  const float* ln1_b  = (const float*)d_in[4];
  const float* W_Q    = (const float*)d_in[5];
  const float* b_Q    = (const float*)d_in[6];
  const float* W_K    = (const float*)d_in[7];
  const float* b_K    = (const float*)d_in[8];
  const float* W_V    = (const float*)d_in[9];
  const float* b_V    = (const float*)d_in[10];
  const float* W_O    = (const float*)d_in[11];
  const float* b_O    = (const float*)d_in[12];
  const float* ln2_w  = (const float*)d_in[13];
  const float* ln2_b  = (const float*)d_in[14];
  const float* W_in   = (const float*)d_in[15];
  const float* b_in   = (const float*)d_in[16];
  const float* W_out  = (const float*)d_in[17];
  const float* b_out  = (const float*)d_in[18];
  const float* lnf_w  = (const float*)d_in[19];
  const float* lnf_b  = (const float*)d_in[20];
  const float* W_U    = (const float*)d_in[21];
  const float* b_U    = (const float*)d_in[22];
  float* out = (float*)d_out;

  float *resid, *bqkv;
  __half *xh, *qkvh, *zh, *hh, *wqkv, *wo, *win, *wout, *wu;
  cudaGetSymbolAddress((void**)&resid, g_resid);
  cudaGetSymbolAddress((void**)&xh,    g_xh);
  cudaGetSymbolAddress((void**)&qkvh,  g_qkvh);
  cudaGetSymbolAddress((void**)&zh,    g_zh);
  cudaGetSymbolAddress((void**)&hh,    g_hh);
  cudaGetSymbolAddress((void**)&wqkv,  g_wqkv);
  cudaGetSymbolAddress((void**)&bqkv,  g_bqkv);
  cudaGetSymbolAddress((void**)&wo,    g_wo);
  cudaGetSymbolAddress((void**)&win,   g_win);
  cudaGetSymbolAddress((void**)&wout,  g_wout);
  cudaGetSymbolAddress((void**)&wu,    g_wu);

  conv_all<<<TOTAL_UNITS / 256, 256>>>(W_U, W_Q, W_K, W_V, W_O, W_in, W_out,
                                       wu, wqkv, wo, win, wout);
  pack_bias_qkv<<<(N_LAYERS * QKV_N) / 256, 256>>>(b_Q, b_K, b_V, bqkv);

  dim3 gA(S_LEN / 64, N_HEADS, 2);

  for (int l = 0; l < N_LAYERS; l++) {
    size_t w1 = (size_t)l * D_MODEL * D_MODEL;
    size_t w2 = (size_t)l * D_MODEL * D_MLP;
    const float* l1w = ln1_w + (size_t)l * D_MODEL;
    const float* l1b = ln1_b + (size_t)l * D_MODEL;
    const float* l2w = ln2_w + (size_t)l * D_MODEL;
    const float* l2b = ln2_b + (size_t)l * D_MODEL;

    if (l == 0) {
      embed_ln_kernel<<<N_TOKENS, 128>>>(tokens, W_E, W_pos, l1w, l1b, resid, xh);
    } else {
      ln_kernel<<<N_TOKENS, 128>>>(resid, l1w, l1b, xh);
    }
    launch_hgemm<false, false, true, false>(xh, wqkv + (size_t)l * D_MODEL * QKV_N,
                                            bqkv + (size_t)l * QKV_N, qkvh,
                                            N_TOKENS, D_MODEL, QKV_N, QKV_N);
    attn_tc<<<gA, 128>>>(qkvh, zh);
    launch_hgemm<false, true, false, false>(zh, wo + w1, b_O + (size_t)l * D_MODEL, resid,
                                            N_TOKENS, D_MODEL, D_MODEL, D_MODEL);
    ln_kernel<<<N_TOKENS, 128>>>(resid, l2w, l2b, xh);
    launch_hgemm<true, false, true, false>(xh, win + w2, b_in + (size_t)l * D_MLP, hh,
                                           N_TOKENS, D_MODEL, D_MLP, D_MLP);
    launch_hgemm<false, true, false, false>(hh, wout + w2, b_out + (size_t)l * D_MODEL, resid,
                                            N_TOKENS, D_MLP, D_MODEL, D_MODEL);
  }

  ln_kernel<<<N_TOKENS, 128>>>(resid, lnf_w, lnf_b, xh);
  launch_hgemm<false, false, false, true>(xh, wu, b_U, out,
                                          N_TOKENS, D_MODEL, N_VOCAB_PAD, N_VOCAB);
}